// round 1
// baseline (speedup 1.0000x reference)
#include <cuda_runtime.h>
#include <math.h>

#define BB 2
#define SS 2048
#define DD 768
#define HH 12
#define DKK 64
#define DFF 3072
#define MROWS (BB*SS)   // 4096

// ---------------- scratch (device globals: allocation-free) ----------------
__device__ float g_ln1 [MROWS*DD];
__device__ float g_q   [MROWS*DD];
__device__ float g_k   [MROWS*DD];
__device__ float g_v   [MROWS*DD];
__device__ float g_attn[MROWS*DD];
__device__ float g_x1  [MROWS*DD];
__device__ float g_ln2 [MROWS*DD];
__device__ float g_ffn1[MROWS*DFF];

// ---------------- LayerNorm: one block per row ----------------
__global__ void ln_kernel(const float* __restrict__ x,
                          const float* __restrict__ gamma,
                          const float* __restrict__ beta,
                          float* __restrict__ out)
{
    int row = blockIdx.x;
    const float* xr = x + (size_t)row * DD;
    int tid = threadIdx.x;

    float a = xr[tid], b = xr[tid + 256], c = xr[tid + 512];
    float s  = a + b + c;
    float ss = a*a + b*b + c*c;
    #pragma unroll
    for (int off = 16; off > 0; off >>= 1) {
        s  += __shfl_xor_sync(0xffffffffu, s,  off);
        ss += __shfl_xor_sync(0xffffffffu, ss, off);
    }
    __shared__ float sh0[8], sh1[8];
    int wid = tid >> 5, lane = tid & 31;
    if (lane == 0) { sh0[wid] = s; sh1[wid] = ss; }
    __syncthreads();
    float tot = 0.f, tot2 = 0.f;
    #pragma unroll
    for (int i = 0; i < 8; i++) { tot += sh0[i]; tot2 += sh1[i]; }
    float mean = tot * (1.0f / DD);
    float var  = tot2 * (1.0f / DD) - mean * mean;
    float rstd = rsqrtf(var + 1e-7f);

    float* orow = out + (size_t)row * DD;
    orow[tid      ] = gamma[tid      ] * (a - mean) * rstd + beta[tid      ];
    orow[tid + 256] = gamma[tid + 256] * (b - mean) * rstd + beta[tid + 256];
    orow[tid + 512] = gamma[tid + 512] * (c - mean) * rstd + beta[tid + 512];
}

// ---------------- GEMM body: C[M,N] = A[M,K] @ W[K,N] + bias (+epilogue) ----
// BM=128 fixed, BK=8, 256 threads (16x16), per-thread 8 x TN.
// EPI: 0 = bias, 1 = bias + residual, 2 = bias + exact GELU
__device__ __forceinline__ float gelu_exact(float v) {
    return 0.5f * v * (1.0f + erff(v * 0.70710678118654752f));
}

template<int BN, int TN, int EPI>
__device__ __forceinline__ void gemm_body(
    const float* __restrict__ A, const float* __restrict__ W,
    const float* __restrict__ bias, const float* __restrict__ resid,
    float* __restrict__ C, int K, int N)
{
    __shared__ float As[8][128];
    __shared__ float Bs[8][BN];

    const int tid = threadIdx.x;
    const int rowBase = blockIdx.y * 128;
    const int colBase = blockIdx.x * BN;

    const int aRow = tid >> 1;
    const int aK   = (tid & 1) * 4;
    const int ty   = tid >> 4;        // 0..15
    const int tx   = tid & 15;        // 0..15

    float acc[8][TN];
    #pragma unroll
    for (int i = 0; i < 8; i++)
        #pragma unroll
        for (int j = 0; j < TN; j++) acc[i][j] = 0.f;

    const int BQ = (8 * BN) / 4;          // # float4 in B tile (<=256)
    const int bRow = tid / (BN / 4);
    const int bCol = (tid % (BN / 4)) * 4;

    for (int k0 = 0; k0 < K; k0 += 8) {
        float4 av = *(const float4*)(A + (size_t)(rowBase + aRow) * K + k0 + aK);
        float4 bv;
        if (tid < BQ)
            bv = *(const float4*)(W + (size_t)(k0 + bRow) * N + colBase + bCol);

        __syncthreads();
        As[aK + 0][aRow] = av.x;
        As[aK + 1][aRow] = av.y;
        As[aK + 2][aRow] = av.z;
        As[aK + 3][aRow] = av.w;
        if (tid < BQ) *(float4*)&Bs[bRow][bCol] = bv;
        __syncthreads();

        #pragma unroll
        for (int kk = 0; kk < 8; kk++) {
            float ar[8], br[TN];
            #pragma unroll
            for (int i = 0; i < 8; i++) ar[i] = As[kk][ty * 8 + i];
            #pragma unroll
            for (int j = 0; j < TN; j++) br[j] = Bs[kk][tx * TN + j];
            #pragma unroll
            for (int i = 0; i < 8; i++)
                #pragma unroll
                for (int j = 0; j < TN; j++)
                    acc[i][j] += ar[i] * br[j];
        }
    }

    #pragma unroll
    for (int i = 0; i < 8; i++) {
        size_t r = rowBase + ty * 8 + i;
        float* crow = C + r * N + colBase + tx * TN;
        const float* rrow = (EPI == 1) ? (resid + r * N + colBase + tx * TN) : nullptr;
        #pragma unroll
        for (int j = 0; j < TN; j += 4) {
            float4 o;
            float v0 = acc[i][j + 0] + bias[colBase + tx * TN + j + 0];
            float v1 = acc[i][j + 1] + bias[colBase + tx * TN + j + 1];
            float v2 = acc[i][j + 2] + bias[colBase + tx * TN + j + 2];
            float v3 = acc[i][j + 3] + bias[colBase + tx * TN + j + 3];
            if (EPI == 1) { v0 += rrow[j+0]; v1 += rrow[j+1]; v2 += rrow[j+2]; v3 += rrow[j+3]; }
            if (EPI == 2) { v0 = gelu_exact(v0); v1 = gelu_exact(v1); v2 = gelu_exact(v2); v3 = gelu_exact(v3); }
            o.x = v0; o.y = v1; o.z = v2; o.w = v3;
            *(float4*)(crow + j) = o;
        }
    }
}

template<int BN, int TN, int EPI>
__global__ void __launch_bounds__(256)
sgemm(const float* __restrict__ A, const float* __restrict__ W,
      const float* __restrict__ bias, const float* __restrict__ resid,
      float* __restrict__ C, int K, int N)
{
    gemm_body<BN, TN, EPI>(A, W, bias, resid, C, K, N);
}

// QKV: one launch, blockIdx.z selects the projection
__global__ void __launch_bounds__(256)
sgemm_qkv(const float* __restrict__ A,
          const float* __restrict__ wq, const float* __restrict__ wk, const float* __restrict__ wv,
          const float* __restrict__ bq, const float* __restrict__ bk, const float* __restrict__ bv,
          float* __restrict__ qo, float* __restrict__ ko, float* __restrict__ vo,
          int K, int N)
{
    const float* W  = (blockIdx.z == 0) ? wq : (blockIdx.z == 1) ? wk : wv;
    const float* bi = (blockIdx.z == 0) ? bq : (blockIdx.z == 1) ? bk : bv;
    float*       C  = (blockIdx.z == 0) ? qo : (blockIdx.z == 1) ? ko : vo;
    gemm_body<128, 8, 0>(A, W, bi, nullptr, C, K, N);
}

// ---------------- causal flash attention (fp32) ----------------
// grid: (B*H, S/128); 128 threads, one query per thread; 64x64 K/V tiles.
__global__ void __launch_bounds__(128)
attn_kernel(const float* __restrict__ q, const float* __restrict__ k,
            const float* __restrict__ v, float* __restrict__ o)
{
    __shared__ float KV[2][64][64];   // [0]=K tile, [1]=V tile

    const int bh = blockIdx.x;
    const int b  = bh / HH;
    const int h  = bh % HH;
    const int tile = (gridDim.y - 1) - blockIdx.y;   // heavy tiles scheduled first
    const int q0 = tile * 128;
    const int tid = threadIdx.x;
    const int qi = q0 + tid;
    const size_t headOff = (size_t)h * DKK;

    // stage Q tile coalesced through shared, then copy my row to registers
    float* stage = &KV[0][0][0];      // 8192 floats = exactly the 128x64 Q tile
    for (int i = tid; i < 128 * 64; i += 128) {
        int r = i >> 6, d = i & 63;
        stage[i] = q[((size_t)(b * SS + q0 + r)) * DD + headOff + d];
    }
    __syncthreads();
    float qr[64];
    #pragma unroll
    for (int d = 0; d < 64; d++) qr[d] = stage[tid * 64 + d] * 0.125f;  // 1/sqrt(64)

    float acc[64];
    #pragma unroll
    for (int d = 0; d < 64; d++) acc[d] = 0.f;
    float m = -INFINITY, l = 0.f;

    const int nkt = 2 * tile + 2;     // key tiles covering keys [0, q0+128)
    for (int kt = 0; kt < nkt; kt++) {
        const int j0 = kt * 64;
        __syncthreads();
        for (int i = tid; i < 64 * 64; i += 128) {
            int r = i >> 6, d = i & 63;
            size_t off = ((size_t)(b * SS + j0 + r)) * DD + headOff + d;
            KV[0][r][d] = k[off];
            KV[1][r][d] = v[off];
        }
        __syncthreads();

        const int jmax = min(64, qi - j0 + 1);   // causal: key <= query
        for (int j = 0; j < jmax; j++) {
            float s0 = 0.f, s1 = 0.f, s2 = 0.f, s3 = 0.f;
            #pragma unroll
            for (int d = 0; d < 64; d += 4) {
                s0 += qr[d + 0] * KV[0][j][d + 0];
                s1 += qr[d + 1] * KV[0][j][d + 1];
                s2 += qr[d + 2] * KV[0][j][d + 2];
                s3 += qr[d + 3] * KV[0][j][d + 3];
            }
            float s = (s0 + s1) + (s2 + s3);
            float p;
            if (s > m) {
                float f = __expf(m - s);
                l *= f;
                #pragma unroll
                for (int d = 0; d < 64; d++) acc[d] *= f;
                m = s;
                p = 1.f;
            } else {
                p = __expf(s - m);
            }
            l += p;
            #pragma unroll
            for (int d = 0; d < 64; d++) acc[d] += p * KV[1][j][d];
        }
    }

    const float inv = 1.f / l;
    float* orow = o + ((size_t)(b * SS + qi)) * DD + headOff;
    #pragma unroll
    for (int d = 0; d < 64; d++) orow[d] = acc[d] * inv;
}

// ---------------- host launcher ----------------
extern "C" void kernel_launch(void* const* d_in, const int* in_sizes, int n_in,
                              void* d_out, int out_size)
{
    const float* x    = (const float*)d_in[0];
    const float* ln1g = (const float*)d_in[1];
    const float* ln1b = (const float*)d_in[2];
    const float* wq   = (const float*)d_in[3];
    const float* bq   = (const float*)d_in[4];
    const float* wk   = (const float*)d_in[5];
    const float* bk   = (const float*)d_in[6];
    const float* wv   = (const float*)d_in[7];
    const float* bv   = (const float*)d_in[8];
    const float* wo   = (const float*)d_in[9];
    const float* bo   = (const float*)d_in[10];
    const float* ln2g = (const float*)d_in[11];
    const float* ln2b = (const float*)d_in[12];
    const float* w1   = (const float*)d_in[13];
    const float* b1   = (const float*)d_in[14];
    const float* w2   = (const float*)d_in[15];
    const float* b2   = (const float*)d_in[16];
    float* out = (float*)d_out;

    float *ln1, *qb, *kb, *vb, *attn, *x1, *ln2, *ffn1;
    cudaGetSymbolAddress((void**)&ln1,  g_ln1);
    cudaGetSymbolAddress((void**)&qb,   g_q);
    cudaGetSymbolAddress((void**)&kb,   g_k);
    cudaGetSymbolAddress((void**)&vb,   g_v);
    cudaGetSymbolAddress((void**)&attn, g_attn);
    cudaGetSymbolAddress((void**)&x1,   g_x1);
    cudaGetSymbolAddress((void**)&ln2,  g_ln2);
    cudaGetSymbolAddress((void**)&ffn1, g_ffn1);

    // 1) LN1
    ln_kernel<<<MROWS, 256>>>(x, ln1g, ln1b, ln1);

    // 2) QKV projections (one fat launch: grid.z selects projection)
    sgemm_qkv<<<dim3(DD / 128, MROWS / 128, 3), 256>>>(
        ln1, wq, wk, wv, bq, bk, bv, qb, kb, vb, DD, DD);

    // 3) causal attention
    attn_kernel<<<dim3(BB * HH, SS / 128), 128>>>(qb, kb, vb, attn);

    // 4) O projection + residual (x1 = x + attn @ wo + bo)
    sgemm<64, 4, 1><<<dim3(DD / 64, MROWS / 128), 256>>>(
        attn, wo, bo, x, x1, DD, DD);

    // 5) LN2
    ln_kernel<<<MROWS, 256>>>(x1, ln2g, ln2b, ln2);

    // 6) FFN up + exact GELU
    sgemm<128, 8, 2><<<dim3(DFF / 128, MROWS / 128), 256>>>(
        ln2, w1, b1, nullptr, ffn1, DD, DFF);

    // 7) FFN down + residual -> final output
    sgemm<64, 4, 1><<<dim3(DD / 64, MROWS / 128), 256>>>(
        ffn1, w2, b2, x1, out, DFF, DD);
}

// round 2
// speedup vs baseline: 1.7572x; 1.7572x over previous
#include <cuda_runtime.h>
#include <math.h>
#include <stdint.h>

#define BB 2
#define SS 2048
#define DD 768
#define HH 12
#define DKK 64
#define DFF 3072
#define MROWS (BB*SS)   // 4096

// ---------------- scratch (device globals: allocation-free) ----------------
__device__ float g_ln1 [MROWS*DD];
__device__ float g_q   [MROWS*DD];
__device__ float g_k   [MROWS*DD];
__device__ float g_v   [MROWS*DD];
__device__ float g_attn[MROWS*DD];
__device__ float g_x1  [MROWS*DD];
__device__ float g_ln2 [MROWS*DD];
__device__ float g_ffn1[MROWS*DFF];

// ---------------- LayerNorm: one block per row ----------------
__global__ void ln_kernel(const float* __restrict__ x,
                          const float* __restrict__ gamma,
                          const float* __restrict__ beta,
                          float* __restrict__ out)
{
    int row = blockIdx.x;
    const float* xr = x + (size_t)row * DD;
    int tid = threadIdx.x;

    float a = xr[tid], b = xr[tid + 256], c = xr[tid + 512];
    float s  = a + b + c;
    float ss = a*a + b*b + c*c;
    #pragma unroll
    for (int off = 16; off > 0; off >>= 1) {
        s  += __shfl_xor_sync(0xffffffffu, s,  off);
        ss += __shfl_xor_sync(0xffffffffu, ss, off);
    }
    __shared__ float sh0[8], sh1[8];
    int wid = tid >> 5, lane = tid & 31;
    if (lane == 0) { sh0[wid] = s; sh1[wid] = ss; }
    __syncthreads();
    float tot = 0.f, tot2 = 0.f;
    #pragma unroll
    for (int i = 0; i < 8; i++) { tot += sh0[i]; tot2 += sh1[i]; }
    float mean = tot * (1.0f / DD);
    float var  = tot2 * (1.0f / DD) - mean * mean;
    float rstd = rsqrtf(var + 1e-7f);

    float* orow = out + (size_t)row * DD;
    orow[tid      ] = gamma[tid      ] * (a - mean) * rstd + beta[tid      ];
    orow[tid + 256] = gamma[tid + 256] * (b - mean) * rstd + beta[tid + 256];
    orow[tid + 512] = gamma[tid + 512] * (c - mean) * rstd + beta[tid + 512];
}

// ---------------- tf32 tensor-core GEMM ----------------
// C[M,N] = A[M,K] @ W[K,N] + bias (+epilogue). BM=BN=128, BK=16, 256 thr.
// Warp grid 2x4, warp tile 64x32, mma.sync m16n8k8 tf32.
// EPI: 0 = bias, 1 = bias + residual, 2 = bias + exact GELU

__device__ __forceinline__ float gelu_exact(float v) {
    return 0.5f * v * (1.0f + erff(v * 0.70710678118654752f));
}

__device__ __forceinline__ void cp_async16(void* smem, const void* gmem) {
    uint32_t s = (uint32_t)__cvta_generic_to_shared(smem);
    asm volatile("cp.async.cg.shared.global [%0], [%1], 16;\n" :: "r"(s), "l"(gmem));
}
#define CP_COMMIT() asm volatile("cp.async.commit_group;\n" ::)
#define CP_WAIT(n)  asm volatile("cp.async.wait_group %0;\n" :: "n"(n))

__device__ __forceinline__ uint32_t f2tf(float x) {
    uint32_t r; asm("cvt.rna.tf32.f32 %0, %1;\n" : "=r"(r) : "f"(x)); return r;
}

__device__ __forceinline__ void mma_tf32(float* c, const uint32_t* a, const uint32_t* b) {
    asm volatile(
      "mma.sync.aligned.m16n8k8.row.col.f32.tf32.tf32.f32 "
      "{%0,%1,%2,%3}, {%4,%5,%6,%7}, {%8,%9}, {%0,%1,%2,%3};\n"
      : "+f"(c[0]), "+f"(c[1]), "+f"(c[2]), "+f"(c[3])
      : "r"(a[0]), "r"(a[1]), "r"(a[2]), "r"(a[3]), "r"(b[0]), "r"(b[1]));
}

template<int EPI>
__device__ __forceinline__ void tgemm_body(
    const float* __restrict__ A, const float* __restrict__ W,
    const float* __restrict__ bias, const float* __restrict__ resid,
    float* __restrict__ C, int K, int N)
{
    __shared__ float As[2][128][20];   // [m][k] layout, stride 20 -> conflict-free frags
    __shared__ float Bs[2][16][136];   // [k][n] layout, stride 136 -> conflict-free frags

    const int tid  = threadIdx.x;
    const int wid  = tid >> 5;
    const int lane = tid & 31;
    const int lr   = lane >> 2;   // 0..7
    const int lc   = lane & 3;    // 0..3
    const int wm   = wid >> 2;    // 0..1
    const int wn   = wid & 3;     // 0..3

    const int rowBase = blockIdx.y * 128;
    const int colBase = blockIdx.x * 128;

    float acc[4][4][4];
    #pragma unroll
    for (int i = 0; i < 4; i++)
        #pragma unroll
        for (int j = 0; j < 4; j++)
            #pragma unroll
            for (int q = 0; q < 4; q++) acc[i][j][q] = 0.f;

    // tile loaders: 512 x 16B chunks each for A and B, 2 per thread
    auto load_tiles = [&](int buf, int k0) {
        #pragma unroll
        for (int i = 0; i < 2; i++) {
            int c = tid + i * 256;
            int m = c >> 2, kq = (c & 3) * 4;
            cp_async16(&As[buf][m][kq], A + (size_t)(rowBase + m) * K + k0 + kq);
        }
        #pragma unroll
        for (int i = 0; i < 2; i++) {
            int c = tid + i * 256;
            int kr = c >> 5, nq = (c & 31) * 4;
            cp_async16(&Bs[buf][kr][nq], W + (size_t)(k0 + kr) * N + colBase + nq);
        }
    };

    const int niter = K >> 4;
    load_tiles(0, 0);
    CP_COMMIT();

    for (int it = 0; it < niter; it++) {
        const int buf = it & 1;
        if (it + 1 < niter) {
            load_tiles(buf ^ 1, (it + 1) << 4);
            CP_COMMIT();
            CP_WAIT(1);
        } else {
            CP_WAIT(0);
        }
        __syncthreads();

        #pragma unroll
        for (int ks = 0; ks < 2; ks++) {
            const int kk = ks * 8;
            uint32_t b[4][2];
            #pragma unroll
            for (int j = 0; j < 4; j++) {
                const int n = wn * 32 + j * 8 + lr;
                b[j][0] = f2tf(Bs[buf][kk + lc    ][n]);
                b[j][1] = f2tf(Bs[buf][kk + 4 + lc][n]);
            }
            #pragma unroll
            for (int i = 0; i < 4; i++) {
                const int m = wm * 64 + i * 16;
                uint32_t a[4];
                a[0] = f2tf(As[buf][m + lr    ][kk + lc    ]);
                a[1] = f2tf(As[buf][m + 8 + lr][kk + lc    ]);
                a[2] = f2tf(As[buf][m + lr    ][kk + 4 + lc]);
                a[3] = f2tf(As[buf][m + 8 + lr][kk + 4 + lc]);
                #pragma unroll
                for (int j = 0; j < 4; j++) mma_tf32(acc[i][j], a, b[j]);
            }
        }
        __syncthreads();
    }

    // epilogue
    const int row0 = rowBase + wm * 64;
    const int col0 = colBase + wn * 32;
    #pragma unroll
    for (int j = 0; j < 4; j++) {
        const int col = col0 + j * 8 + lc * 2;
        const float b0v = bias[col], b1v = bias[col + 1];
        #pragma unroll
        for (int i = 0; i < 4; i++) {
            const int r0 = row0 + i * 16 + lr;
            float v0 = acc[i][j][0] + b0v;
            float v1 = acc[i][j][1] + b1v;
            float v2 = acc[i][j][2] + b0v;
            float v3 = acc[i][j][3] + b1v;
            if (EPI == 1) {
                v0 += resid[(size_t)r0 * N + col];
                v1 += resid[(size_t)r0 * N + col + 1];
                v2 += resid[(size_t)(r0 + 8) * N + col];
                v3 += resid[(size_t)(r0 + 8) * N + col + 1];
            }
            if (EPI == 2) {
                v0 = gelu_exact(v0); v1 = gelu_exact(v1);
                v2 = gelu_exact(v2); v3 = gelu_exact(v3);
            }
            *(float2*)&C[(size_t)r0 * N + col]       = make_float2(v0, v1);
            *(float2*)&C[(size_t)(r0 + 8) * N + col] = make_float2(v2, v3);
        }
    }
}

template<int EPI>
__global__ void __launch_bounds__(256, 2)
tgemm(const float* __restrict__ A, const float* __restrict__ W,
      const float* __restrict__ bias, const float* __restrict__ resid,
      float* __restrict__ C, int K, int N)
{
    tgemm_body<EPI>(A, W, bias, resid, C, K, N);
}

// QKV: one launch, blockIdx.z selects the projection
__global__ void __launch_bounds__(256, 2)
tgemm_qkv(const float* __restrict__ A,
          const float* __restrict__ wq, const float* __restrict__ wk, const float* __restrict__ wv,
          const float* __restrict__ bq, const float* __restrict__ bk, const float* __restrict__ bv,
          float* __restrict__ qo, float* __restrict__ ko, float* __restrict__ vo,
          int K, int N)
{
    const float* W  = (blockIdx.z == 0) ? wq : (blockIdx.z == 1) ? wk : wv;
    const float* bi = (blockIdx.z == 0) ? bq : (blockIdx.z == 1) ? bk : bv;
    float*       C  = (blockIdx.z == 0) ? qo : (blockIdx.z == 1) ? ko : vo;
    tgemm_body<0>(A, W, bi, nullptr, C, K, N);
}

// ---------------- causal flash attention (fp32 SIMT, unchanged) ----------------
__global__ void __launch_bounds__(128)
attn_kernel(const float* __restrict__ q, const float* __restrict__ k,
            const float* __restrict__ v, float* __restrict__ o)
{
    __shared__ float KV[2][64][64];   // [0]=K tile, [1]=V tile

    const int bh = blockIdx.x;
    const int b  = bh / HH;
    const int h  = bh % HH;
    const int tile = (gridDim.y - 1) - blockIdx.y;   // heavy tiles first
    const int q0 = tile * 128;
    const int tid = threadIdx.x;
    const int qi = q0 + tid;
    const size_t headOff = (size_t)h * DKK;

    float* stage = &KV[0][0][0];
    for (int i = tid; i < 128 * 64; i += 128) {
        int r = i >> 6, d = i & 63;
        stage[i] = q[((size_t)(b * SS + q0 + r)) * DD + headOff + d];
    }
    __syncthreads();
    float qr[64];
    #pragma unroll
    for (int d = 0; d < 64; d++) qr[d] = stage[tid * 64 + d] * 0.125f;

    float acc[64];
    #pragma unroll
    for (int d = 0; d < 64; d++) acc[d] = 0.f;
    float m = -INFINITY, l = 0.f;

    const int nkt = 2 * tile + 2;
    for (int kt = 0; kt < nkt; kt++) {
        const int j0 = kt * 64;
        __syncthreads();
        for (int i = tid; i < 64 * 64; i += 128) {
            int r = i >> 6, d = i & 63;
            size_t off = ((size_t)(b * SS + j0 + r)) * DD + headOff + d;
            KV[0][r][d] = k[off];
            KV[1][r][d] = v[off];
        }
        __syncthreads();

        const int jmax = min(64, qi - j0 + 1);
        for (int j = 0; j < jmax; j++) {
            float s0 = 0.f, s1 = 0.f, s2 = 0.f, s3 = 0.f;
            #pragma unroll
            for (int d = 0; d < 64; d += 4) {
                s0 += qr[d + 0] * KV[0][j][d + 0];
                s1 += qr[d + 1] * KV[0][j][d + 1];
                s2 += qr[d + 2] * KV[0][j][d + 2];
                s3 += qr[d + 3] * KV[0][j][d + 3];
            }
            float s = (s0 + s1) + (s2 + s3);
            float p;
            if (s > m) {
                float f = __expf(m - s);
                l *= f;
                #pragma unroll
                for (int d = 0; d < 64; d++) acc[d] *= f;
                m = s;
                p = 1.f;
            } else {
                p = __expf(s - m);
            }
            l += p;
            #pragma unroll
            for (int d = 0; d < 64; d++) acc[d] += p * KV[1][j][d];
        }
    }

    const float inv = 1.f / l;
    float* orow = o + ((size_t)(b * SS + qi)) * DD + headOff;
    #pragma unroll
    for (int d = 0; d < 64; d++) orow[d] = acc[d] * inv;
}

// ---------------- host launcher ----------------
extern "C" void kernel_launch(void* const* d_in, const int* in_sizes, int n_in,
                              void* d_out, int out_size)
{
    const float* x    = (const float*)d_in[0];
    const float* ln1g = (const float*)d_in[1];
    const float* ln1b = (const float*)d_in[2];
    const float* wq   = (const float*)d_in[3];
    const float* bq   = (const float*)d_in[4];
    const float* wk   = (const float*)d_in[5];
    const float* bk   = (const float*)d_in[6];
    const float* wv   = (const float*)d_in[7];
    const float* bv   = (const float*)d_in[8];
    const float* wo   = (const float*)d_in[9];
    const float* bo   = (const float*)d_in[10];
    const float* ln2g = (const float*)d_in[11];
    const float* ln2b = (const float*)d_in[12];
    const float* w1   = (const float*)d_in[13];
    const float* b1   = (const float*)d_in[14];
    const float* w2   = (const float*)d_in[15];
    const float* b2   = (const float*)d_in[16];
    float* out = (float*)d_out;

    float *ln1, *qb, *kb, *vb, *attn, *x1, *ln2, *ffn1;
    cudaGetSymbolAddress((void**)&ln1,  g_ln1);
    cudaGetSymbolAddress((void**)&qb,   g_q);
    cudaGetSymbolAddress((void**)&kb,   g_k);
    cudaGetSymbolAddress((void**)&vb,   g_v);
    cudaGetSymbolAddress((void**)&attn, g_attn);
    cudaGetSymbolAddress((void**)&x1,   g_x1);
    cudaGetSymbolAddress((void**)&ln2,  g_ln2);
    cudaGetSymbolAddress((void**)&ffn1, g_ffn1);

    // 1) LN1
    ln_kernel<<<MROWS, 256>>>(x, ln1g, ln1b, ln1);

    // 2) QKV projections (tensor cores, one fat launch)
    tgemm_qkv<<<dim3(DD / 128, MROWS / 128, 3), 256>>>(
        ln1, wq, wk, wv, bq, bk, bv, qb, kb, vb, DD, DD);

    // 3) causal attention
    attn_kernel<<<dim3(BB * HH, SS / 128), 128>>>(qb, kb, vb, attn);

    // 4) O projection + residual (x1 = x + attn @ wo + bo)
    tgemm<1><<<dim3(DD / 128, MROWS / 128), 256>>>(attn, wo, bo, x, x1, DD, DD);

    // 5) LN2
    ln_kernel<<<MROWS, 256>>>(x1, ln2g, ln2b, ln2);

    // 6) FFN up + exact GELU
    tgemm<2><<<dim3(DFF / 128, MROWS / 128), 256>>>(ln2, w1, b1, nullptr, ffn1, DD, DFF);

    // 7) FFN down + residual -> final output
    tgemm<1><<<dim3(DD / 128, MROWS / 128), 256>>>(ffn1, w2, b2, x1, out, DFF, DD);
}

// round 4
// speedup vs baseline: 3.3589x; 1.9115x over previous
#include <cuda_runtime.h>
#include <cuda_fp16.h>
#include <math.h>
#include <stdint.h>

#define BB 2
#define SS 2048
#define DD 768
#define HH 12
#define DKK 64
#define DFF 3072
#define MROWS (BB*SS)   // 4096

// ---------------- scratch (device globals: allocation-free) ----------------
__device__ float g_ln1 [MROWS*DD];
__device__ float g_q   [MROWS*DD];
__device__ float g_k   [MROWS*DD];
__device__ float g_v   [MROWS*DD];
__device__ float g_attn[MROWS*DD];
__device__ float g_x1  [MROWS*DD];
__device__ float g_ln2 [MROWS*DD];
__device__ float g_ffn1[MROWS*DFF];

// ---------------- LayerNorm: one block per row ----------------
__global__ void ln_kernel(const float* __restrict__ x,
                          const float* __restrict__ gamma,
                          const float* __restrict__ beta,
                          float* __restrict__ out)
{
    int row = blockIdx.x;
    const float* xr = x + (size_t)row * DD;
    int tid = threadIdx.x;

    float a = xr[tid], b = xr[tid + 256], c = xr[tid + 512];
    float s  = a + b + c;
    float ss = a*a + b*b + c*c;
    #pragma unroll
    for (int off = 16; off > 0; off >>= 1) {
        s  += __shfl_xor_sync(0xffffffffu, s,  off);
        ss += __shfl_xor_sync(0xffffffffu, ss, off);
    }
    __shared__ float sh0[8], sh1[8];
    int wid = tid >> 5, lane = tid & 31;
    if (lane == 0) { sh0[wid] = s; sh1[wid] = ss; }
    __syncthreads();
    float tot = 0.f, tot2 = 0.f;
    #pragma unroll
    for (int i = 0; i < 8; i++) { tot += sh0[i]; tot2 += sh1[i]; }
    float mean = tot * (1.0f / DD);
    float var  = tot2 * (1.0f / DD) - mean * mean;
    float rstd = rsqrtf(var + 1e-7f);

    float* orow = out + (size_t)row * DD;
    orow[tid      ] = gamma[tid      ] * (a - mean) * rstd + beta[tid      ];
    orow[tid + 256] = gamma[tid + 256] * (b - mean) * rstd + beta[tid + 256];
    orow[tid + 512] = gamma[tid + 512] * (c - mean) * rstd + beta[tid + 512];
}

// ---------------- common PTX helpers ----------------
__device__ __forceinline__ float gelu_exact(float v) {
    return 0.5f * v * (1.0f + erff(v * 0.70710678118654752f));
}

__device__ __forceinline__ void cp_async16(void* smem, const void* gmem) {
    uint32_t s = (uint32_t)__cvta_generic_to_shared(smem);
    asm volatile("cp.async.cg.shared.global [%0], [%1], 16;\n" :: "r"(s), "l"(gmem));
}
#define CP_COMMIT() asm volatile("cp.async.commit_group;\n" ::)
#define CP_WAIT(n)  asm volatile("cp.async.wait_group %0;\n" :: "n"(n))

__device__ __forceinline__ uint32_t f2tf(float x) {
    uint32_t r; asm("cvt.rna.tf32.f32 %0, %1;\n" : "=r"(r) : "f"(x)); return r;
}

__device__ __forceinline__ void mma_tf32(float* c, const uint32_t* a, const uint32_t* b) {
    asm volatile(
      "mma.sync.aligned.m16n8k8.row.col.f32.tf32.tf32.f32 "
      "{%0,%1,%2,%3}, {%4,%5,%6,%7}, {%8,%9}, {%0,%1,%2,%3};\n"
      : "+f"(c[0]), "+f"(c[1]), "+f"(c[2]), "+f"(c[3])
      : "r"(a[0]), "r"(a[1]), "r"(a[2]), "r"(a[3]), "r"(b[0]), "r"(b[1]));
}

__device__ __forceinline__ void mma_f16(float* c, const uint32_t* a, uint32_t b0, uint32_t b1) {
    asm volatile(
      "mma.sync.aligned.m16n8k16.row.col.f32.f16.f16.f32 "
      "{%0,%1,%2,%3}, {%4,%5,%6,%7}, {%8,%9}, {%0,%1,%2,%3};\n"
      : "+f"(c[0]), "+f"(c[1]), "+f"(c[2]), "+f"(c[3])
      : "r"(a[0]), "r"(a[1]), "r"(a[2]), "r"(a[3]), "r"(b0), "r"(b1));
}

// ---------------- tf32 tensor-core GEMM ----------------
template<int EPI>
__device__ __forceinline__ void tgemm_body(
    const float* __restrict__ A, const float* __restrict__ W,
    const float* __restrict__ bias, const float* __restrict__ resid,
    float* __restrict__ C, int K, int N)
{
    __shared__ float As[2][128][20];
    __shared__ float Bs[2][16][136];

    const int tid  = threadIdx.x;
    const int wid  = tid >> 5;
    const int lane = tid & 31;
    const int lr   = lane >> 2;
    const int lc   = lane & 3;
    const int wm   = wid >> 2;
    const int wn   = wid & 3;

    const int rowBase = blockIdx.y * 128;
    const int colBase = blockIdx.x * 128;

    float acc[4][4][4];
    #pragma unroll
    for (int i = 0; i < 4; i++)
        #pragma unroll
        for (int j = 0; j < 4; j++)
            #pragma unroll
            for (int q = 0; q < 4; q++) acc[i][j][q] = 0.f;

    auto load_tiles = [&](int buf, int k0) {
        #pragma unroll
        for (int i = 0; i < 2; i++) {
            int c = tid + i * 256;
            int m = c >> 2, kq = (c & 3) * 4;
            cp_async16(&As[buf][m][kq], A + (size_t)(rowBase + m) * K + k0 + kq);
        }
        #pragma unroll
        for (int i = 0; i < 2; i++) {
            int c = tid + i * 256;
            int kr = c >> 5, nq = (c & 31) * 4;
            cp_async16(&Bs[buf][kr][nq], W + (size_t)(k0 + kr) * N + colBase + nq);
        }
    };

    const int niter = K >> 4;
    load_tiles(0, 0);
    CP_COMMIT();

    for (int it = 0; it < niter; it++) {
        const int buf = it & 1;
        if (it + 1 < niter) {
            load_tiles(buf ^ 1, (it + 1) << 4);
            CP_COMMIT();
            CP_WAIT(1);
        } else {
            CP_WAIT(0);
        }
        __syncthreads();

        #pragma unroll
        for (int ks = 0; ks < 2; ks++) {
            const int kk = ks * 8;
            uint32_t b[4][2];
            #pragma unroll
            for (int j = 0; j < 4; j++) {
                const int n = wn * 32 + j * 8 + lr;
                b[j][0] = f2tf(Bs[buf][kk + lc    ][n]);
                b[j][1] = f2tf(Bs[buf][kk + 4 + lc][n]);
            }
            #pragma unroll
            for (int i = 0; i < 4; i++) {
                const int m = wm * 64 + i * 16;
                uint32_t a[4];
                a[0] = f2tf(As[buf][m + lr    ][kk + lc    ]);
                a[1] = f2tf(As[buf][m + 8 + lr][kk + lc    ]);
                a[2] = f2tf(As[buf][m + lr    ][kk + 4 + lc]);
                a[3] = f2tf(As[buf][m + 8 + lr][kk + 4 + lc]);
                #pragma unroll
                for (int j = 0; j < 4; j++) mma_tf32(acc[i][j], a, b[j]);
            }
        }
        __syncthreads();
    }

    const int row0 = rowBase + wm * 64;
    const int col0 = colBase + wn * 32;
    #pragma unroll
    for (int j = 0; j < 4; j++) {
        const int col = col0 + j * 8 + lc * 2;
        const float b0v = bias[col], b1v = bias[col + 1];
        #pragma unroll
        for (int i = 0; i < 4; i++) {
            const int r0 = row0 + i * 16 + lr;
            float v0 = acc[i][j][0] + b0v;
            float v1 = acc[i][j][1] + b1v;
            float v2 = acc[i][j][2] + b0v;
            float v3 = acc[i][j][3] + b1v;
            if (EPI == 1) {
                v0 += resid[(size_t)r0 * N + col];
                v1 += resid[(size_t)r0 * N + col + 1];
                v2 += resid[(size_t)(r0 + 8) * N + col];
                v3 += resid[(size_t)(r0 + 8) * N + col + 1];
            }
            if (EPI == 2) {
                v0 = gelu_exact(v0); v1 = gelu_exact(v1);
                v2 = gelu_exact(v2); v3 = gelu_exact(v3);
            }
            *(float2*)&C[(size_t)r0 * N + col]       = make_float2(v0, v1);
            *(float2*)&C[(size_t)(r0 + 8) * N + col] = make_float2(v2, v3);
        }
    }
}

template<int EPI>
__global__ void __launch_bounds__(256, 2)
tgemm(const float* __restrict__ A, const float* __restrict__ W,
      const float* __restrict__ bias, const float* __restrict__ resid,
      float* __restrict__ C, int K, int N)
{
    tgemm_body<EPI>(A, W, bias, resid, C, K, N);
}

__global__ void __launch_bounds__(256, 2)
tgemm_qkv(const float* __restrict__ A,
          const float* __restrict__ wq, const float* __restrict__ wk, const float* __restrict__ wv,
          const float* __restrict__ bq, const float* __restrict__ bk, const float* __restrict__ bv,
          float* __restrict__ qo, float* __restrict__ ko, float* __restrict__ vo,
          int K, int N)
{
    const float* W  = (blockIdx.z == 0) ? wq : (blockIdx.z == 1) ? wk : wv;
    const float* bi = (blockIdx.z == 0) ? bq : (blockIdx.z == 1) ? bk : bv;
    float*       C  = (blockIdx.z == 0) ? qo : (blockIdx.z == 1) ? ko : vo;
    tgemm_body<0>(A, W, bi, nullptr, C, K, N);
}

// ---------------- tensor-core causal flash attention ----------------
// grid (B*H, S/64), 128 threads (4 warps). Each warp owns 16 query rows.
// Q·K^T: m16n8k8 tf32 (Q frags register-resident). P·V: m16n8k16 fp16.
__global__ void __launch_bounds__(128)
attn_tc_kernel(const float* __restrict__ q, const float* __restrict__ k,
               const float* __restrict__ v, float* __restrict__ o)
{
    __shared__ float    Ks[64][68];   // [key][dk] f32, stride 68 -> conflict-free frags
    __shared__ uint32_t Vt[64][36];   // [dk][key-pair] half2, stride 36 -> conflict-free

    const int bh  = blockIdx.x;
    const int b   = bh / HH;
    const int h   = bh % HH;
    const int T   = (gridDim.y - 1) - blockIdx.y;   // heavy tiles first
    const int q0  = T * 64;
    const int tid = threadIdx.x;
    const int wid = tid >> 5;
    const int lane = tid & 31;
    const int lr  = lane >> 2;   // 0..7
    const int lc  = lane & 3;    // 0..3
    const size_t headOff = (size_t)h * DKK;
    const size_t bBase   = (size_t)b * SS;

    // ---- stage Q tile (scaled) into Ks, build register-resident tf32 A frags ----
    for (int i = tid; i < 64 * 64; i += 128) {
        int r = i >> 6, d = i & 63;
        Ks[r][d] = q[(bBase + q0 + r) * DD + headOff + d] * 0.125f;  // 1/sqrt(64)
    }
    __syncthreads();
    uint32_t qf[8][4];
    const int qrow = wid * 16;
    #pragma unroll
    for (int kc = 0; kc < 8; kc++) {
        qf[kc][0] = f2tf(Ks[qrow + lr    ][kc * 8 + lc    ]);
        qf[kc][1] = f2tf(Ks[qrow + 8 + lr][kc * 8 + lc    ]);
        qf[kc][2] = f2tf(Ks[qrow + lr    ][kc * 8 + lc + 4]);
        qf[kc][3] = f2tf(Ks[qrow + 8 + lr][kc * 8 + lc + 4]);
    }

    float oacc[8][4];
    #pragma unroll
    for (int nv = 0; nv < 8; nv++)
        #pragma unroll
        for (int t = 0; t < 4; t++) oacc[nv][t] = 0.f;
    float m0 = -1e30f, m1 = -1e30f, l0 = 0.f, l1 = 0.f;

    for (int kt = 0; kt <= T; kt++) {
        const int j0 = kt * 64;
        __syncthreads();
        // load K tile (f32) and V tile (transposed half) into smem
        for (int i = tid; i < 64 * 16; i += 128) {          // 64 rows x 16 float4
            int r = i >> 4, d4 = (i & 15) * 4;
            float4 kv4 = *(const float4*)(k + (bBase + j0 + r) * DD + headOff + d4);
            Ks[r][d4 + 0] = kv4.x; Ks[r][d4 + 1] = kv4.y;
            Ks[r][d4 + 2] = kv4.z; Ks[r][d4 + 3] = kv4.w;
            float4 vv4 = *(const float4*)(v + (bBase + j0 + r) * DD + headOff + d4);
            __half* vt0 = (__half*)&Vt[d4][0];
            vt0[0 * 72 + r] = __float2half_rn(vv4.x);   // row stride = 36 u32 = 72 half
            vt0[1 * 72 + r] = __float2half_rn(vv4.y);
            vt0[2 * 72 + r] = __float2half_rn(vv4.z);
            vt0[3 * 72 + r] = __float2half_rn(vv4.w);
        }
        __syncthreads();

        // ---- S = Q K^T : 8 n-tiles x 8 k-chunks of m16n8k8 ----
        float sacc[8][4];
        #pragma unroll
        for (int nt = 0; nt < 8; nt++) {
            sacc[nt][0] = sacc[nt][1] = sacc[nt][2] = sacc[nt][3] = 0.f;
            #pragma unroll
            for (int kc = 0; kc < 8; kc++) {
                uint32_t bb[2];
                bb[0] = f2tf(Ks[nt * 8 + lr][kc * 8 + lc    ]);
                bb[1] = f2tf(Ks[nt * 8 + lr][kc * 8 + lc + 4]);
                mma_tf32(sacc[nt], qf[kc], bb);
            }
        }

        // ---- causal mask (only the diagonal tile) ----
        if (kt == T) {
            const int qi0 = qrow + lr, qi1 = qi0 + 8;
            #pragma unroll
            for (int nt = 0; nt < 8; nt++) {
                const int kj = nt * 8 + lc * 2;
                if (kj     > qi0) sacc[nt][0] = -1e30f;
                if (kj + 1 > qi0) sacc[nt][1] = -1e30f;
                if (kj     > qi1) sacc[nt][2] = -1e30f;
                if (kj + 1 > qi1) sacc[nt][3] = -1e30f;
            }
        }

        // ---- online softmax on fragments ----
        float mx0 = -1e30f, mx1 = -1e30f;
        #pragma unroll
        for (int nt = 0; nt < 8; nt++) {
            mx0 = fmaxf(mx0, fmaxf(sacc[nt][0], sacc[nt][1]));
            mx1 = fmaxf(mx1, fmaxf(sacc[nt][2], sacc[nt][3]));
        }
        mx0 = fmaxf(mx0, __shfl_xor_sync(0xffffffffu, mx0, 1));
        mx0 = fmaxf(mx0, __shfl_xor_sync(0xffffffffu, mx0, 2));
        mx1 = fmaxf(mx1, __shfl_xor_sync(0xffffffffu, mx1, 1));
        mx1 = fmaxf(mx1, __shfl_xor_sync(0xffffffffu, mx1, 2));

        const float mn0 = fmaxf(m0, mx0);
        const float mn1 = fmaxf(m1, mx1);
        const float sc0 = __expf(m0 - mn0);
        const float sc1 = __expf(m1 - mn1);
        m0 = mn0; m1 = mn1;

        float la0 = 0.f, la1 = 0.f;
        #pragma unroll
        for (int nt = 0; nt < 8; nt++) {
            sacc[nt][0] = __expf(sacc[nt][0] - mn0);
            sacc[nt][1] = __expf(sacc[nt][1] - mn0);
            sacc[nt][2] = __expf(sacc[nt][2] - mn1);
            sacc[nt][3] = __expf(sacc[nt][3] - mn1);
            la0 += sacc[nt][0] + sacc[nt][1];
            la1 += sacc[nt][2] + sacc[nt][3];
        }
        la0 += __shfl_xor_sync(0xffffffffu, la0, 1);
        la0 += __shfl_xor_sync(0xffffffffu, la0, 2);
        la1 += __shfl_xor_sync(0xffffffffu, la1, 1);
        la1 += __shfl_xor_sync(0xffffffffu, la1, 2);
        l0 = l0 * sc0 + la0;
        l1 = l1 * sc1 + la1;

        #pragma unroll
        for (int nv = 0; nv < 8; nv++) {
            oacc[nv][0] *= sc0; oacc[nv][1] *= sc0;
            oacc[nv][2] *= sc1; oacc[nv][3] *= sc1;
        }

        // ---- pack P to fp16 A frags: pair of n8 S-tiles = one k16 chunk ----
        uint32_t pf[4][4];
        #pragma unroll
        for (int pk = 0; pk < 4; pk++) {
            __half2 h0 = __floats2half2_rn(sacc[2*pk    ][0], sacc[2*pk    ][1]);
            __half2 h1 = __floats2half2_rn(sacc[2*pk    ][2], sacc[2*pk    ][3]);
            __half2 h2 = __floats2half2_rn(sacc[2*pk + 1][0], sacc[2*pk + 1][1]);
            __half2 h3 = __floats2half2_rn(sacc[2*pk + 1][2], sacc[2*pk + 1][3]);
            pf[pk][0] = *(uint32_t*)&h0;
            pf[pk][1] = *(uint32_t*)&h1;
            pf[pk][2] = *(uint32_t*)&h2;
            pf[pk][3] = *(uint32_t*)&h3;
        }

        // ---- O += P V : 8 n-tiles (dk) x 4 k-chunks (keys) of m16n8k16 ----
        #pragma unroll
        for (int nv = 0; nv < 8; nv++) {
            #pragma unroll
            for (int pk = 0; pk < 4; pk++) {
                uint32_t b0 = Vt[nv * 8 + lr][pk * 8 + lc    ];
                uint32_t b1 = Vt[nv * 8 + lr][pk * 8 + lc + 4];
                mma_f16(oacc[nv], pf[pk], b0, b1);
            }
        }
    }

    // ---- normalize and write ----
    const float inv0 = 1.f / l0;
    const float inv1 = 1.f / l1;
    const size_t r0 = bBase + q0 + qrow + lr;
    #pragma unroll
    for (int nv = 0; nv < 8; nv++) {
        const int col = nv * 8 + lc * 2;
        *(float2*)&o[r0 * DD + headOff + col] =
            make_float2(oacc[nv][0] * inv0, oacc[nv][1] * inv0);
        *(float2*)&o[(r0 + 8) * DD + headOff + col] =
            make_float2(oacc[nv][2] * inv1, oacc[nv][3] * inv1);
    }
}

// ---------------- host launcher ----------------
extern "C" void kernel_launch(void* const* d_in, const int* in_sizes, int n_in,
                              void* d_out, int out_size)
{
    const float* x    = (const float*)d_in[0];
    const float* ln1g = (const float*)d_in[1];
    const float* ln1b = (const float*)d_in[2];
    const float* wq   = (const float*)d_in[3];
    const float* bq   = (const float*)d_in[4];
    const float* wk   = (const float*)d_in[5];
    const float* bk   = (const float*)d_in[6];
    const float* wv   = (const float*)d_in[7];
    const float* bv   = (const float*)d_in[8];
    const float* wo   = (const float*)d_in[9];
    const float* bo   = (const float*)d_in[10];
    const float* ln2g = (const float*)d_in[11];
    const float* ln2b = (const float*)d_in[12];
    const float* w1   = (const float*)d_in[13];
    const float* b1   = (const float*)d_in[14];
    const float* w2   = (const float*)d_in[15];
    const float* b2   = (const float*)d_in[16];
    float* out = (float*)d_out;

    float *ln1, *qb, *kb, *vb, *attn, *x1, *ln2, *ffn1;
    cudaGetSymbolAddress((void**)&ln1,  g_ln1);
    cudaGetSymbolAddress((void**)&qb,   g_q);
    cudaGetSymbolAddress((void**)&kb,   g_k);
    cudaGetSymbolAddress((void**)&vb,   g_v);
    cudaGetSymbolAddress((void**)&attn, g_attn);
    cudaGetSymbolAddress((void**)&x1,   g_x1);
    cudaGetSymbolAddress((void**)&ln2,  g_ln2);
    cudaGetSymbolAddress((void**)&ffn1, g_ffn1);

    // 1) LN1
    ln_kernel<<<MROWS, 256>>>(x, ln1g, ln1b, ln1);

    // 2) QKV projections
    tgemm_qkv<<<dim3(DD / 128, MROWS / 128, 3), 256>>>(
        ln1, wq, wk, wv, bq, bk, bv, qb, kb, vb, DD, DD);

    // 3) causal attention (tensor cores)
    attn_tc_kernel<<<dim3(BB * HH, SS / 64), 128>>>(qb, kb, vb, attn);

    // 4) O projection + residual
    tgemm<1><<<dim3(DD / 128, MROWS / 128), 256>>>(attn, wo, bo, x, x1, DD, DD);

    // 5) LN2
    ln_kernel<<<MROWS, 256>>>(x1, ln2g, ln2b, ln2);

    // 6) FFN up + exact GELU
    tgemm<2><<<dim3(DFF / 128, MROWS / 128), 256>>>(ln2, w1, b1, nullptr, ffn1, DD, DFF);

    // 7) FFN down + residual -> final output
    tgemm<1><<<dim3(DD / 128, MROWS / 128), 256>>>(ffn1, w2, b2, x1, out, DFF, DD);
}

// round 5
// speedup vs baseline: 5.7629x; 1.7157x over previous
#include <cuda_runtime.h>
#include <cuda_fp16.h>
#include <math.h>
#include <stdint.h>

#define BB 2
#define SS 2048
#define DD 768
#define HH 12
#define DKK 64
#define DFF 3072
#define MROWS (BB*SS)   // 4096

// ---------------- scratch (device globals: allocation-free) ----------------
__device__ __half h_ln1 [MROWS*DD];
__device__ __half h_q   [MROWS*DD];
__device__ __half h_k   [MROWS*DD];
__device__ __half h_v   [MROWS*DD];
__device__ __half h_attn[MROWS*DD];
__device__ float  g_x1  [MROWS*DD];
__device__ __half h_ln2 [MROWS*DD];
__device__ __half h_ffn1[MROWS*DFF];
// transposed half weights: Wt[N][K]
__device__ __half h_wq[DD*DD];
__device__ __half h_wk[DD*DD];
__device__ __half h_wv[DD*DD];
__device__ __half h_wo[DD*DD];
__device__ __half h_w1[DD*DFF];
__device__ __half h_w2[DFF*DD];

// ---------------- helpers ----------------
__device__ __forceinline__ float gelu_exact(float v) {
    return 0.5f * v * (1.0f + erff(v * 0.70710678118654752f));
}
__device__ __forceinline__ void cp_async16(void* smem, const void* gmem) {
    uint32_t s = (uint32_t)__cvta_generic_to_shared(smem);
    asm volatile("cp.async.cg.shared.global [%0], [%1], 16;\n" :: "r"(s), "l"(gmem));
}
#define CP_COMMIT() asm volatile("cp.async.commit_group;\n" ::)
#define CP_WAIT(n)  asm volatile("cp.async.wait_group %0;\n" :: "n"(n))

__device__ __forceinline__ void mma_f16(float* c, const uint32_t* a, uint32_t b0, uint32_t b1) {
    asm volatile(
      "mma.sync.aligned.m16n8k16.row.col.f32.f16.f16.f32 "
      "{%0,%1,%2,%3}, {%4,%5,%6,%7}, {%8,%9}, {%0,%1,%2,%3};\n"
      : "+f"(c[0]), "+f"(c[1]), "+f"(c[2]), "+f"(c[3])
      : "r"(a[0]), "r"(a[1]), "r"(a[2]), "r"(a[3]), "r"(b0), "r"(b1));
}
__device__ __forceinline__ void ldsm_x4_t(uint32_t& r0, uint32_t& r1, uint32_t& r2, uint32_t& r3,
                                          uint32_t addr) {
    asm volatile("ldmatrix.sync.aligned.m8n8.x4.trans.shared.b16 {%0,%1,%2,%3}, [%4];\n"
      : "=r"(r0), "=r"(r1), "=r"(r2), "=r"(r3) : "r"(addr));
}

// ---------------- weight transpose + f32->f16 convert ----------------
// Wt[n][k] = (half) W[k][n]
__global__ void wconv_t(const float* __restrict__ W, __half* __restrict__ Wt, int K, int N)
{
    __shared__ float t[32][33];
    const int k0 = blockIdx.x * 32, n0 = blockIdx.y * 32;
    const int tx = threadIdx.x, ty = threadIdx.y;   // 32 x 8
    #pragma unroll
    for (int i = 0; i < 32; i += 8)
        t[ty + i][tx] = W[(size_t)(k0 + ty + i) * N + n0 + tx];
    __syncthreads();
    #pragma unroll
    for (int i = 0; i < 32; i += 8)
        Wt[(size_t)(n0 + ty + i) * K + k0 + tx] = __float2half_rn(t[tx][ty + i]);
}

// ---------------- LayerNorm: f32 in, f16 out ----------------
__global__ void ln_kernel(const float* __restrict__ x,
                          const float* __restrict__ gamma,
                          const float* __restrict__ beta,
                          __half* __restrict__ out)
{
    int row = blockIdx.x;
    const float* xr = x + (size_t)row * DD;
    int tid = threadIdx.x;

    float a = xr[tid], b = xr[tid + 256], c = xr[tid + 512];
    float s  = a + b + c;
    float ss = a*a + b*b + c*c;
    #pragma unroll
    for (int off = 16; off > 0; off >>= 1) {
        s  += __shfl_xor_sync(0xffffffffu, s,  off);
        ss += __shfl_xor_sync(0xffffffffu, ss, off);
    }
    __shared__ float sh0[8], sh1[8];
    int wid = tid >> 5, lane = tid & 31;
    if (lane == 0) { sh0[wid] = s; sh1[wid] = ss; }
    __syncthreads();
    float tot = 0.f, tot2 = 0.f;
    #pragma unroll
    for (int i = 0; i < 8; i++) { tot += sh0[i]; tot2 += sh1[i]; }
    float mean = tot * (1.0f / DD);
    float var  = tot2 * (1.0f / DD) - mean * mean;
    float rstd = rsqrtf(var + 1e-7f);

    __half* orow = out + (size_t)row * DD;
    orow[tid      ] = __float2half_rn(gamma[tid      ] * (a - mean) * rstd + beta[tid      ]);
    orow[tid + 256] = __float2half_rn(gamma[tid + 256] * (b - mean) * rstd + beta[tid + 256]);
    orow[tid + 512] = __float2half_rn(gamma[tid + 512] * (c - mean) * rstd + beta[tid + 512]);
}

// ---------------- fp16 tensor-core GEMM ----------------
// C[M,N] = A[M,K](f16) @ Wt[N,K](f16)^T + bias(f32)
// BM=BN=128, BK=32, 256 threads, warps 2x4, warp tile 64x32, m16n8k16.
// EPI: 0 = bias -> half out | 1 = bias + resid -> f32 out | 2 = bias + GELU -> half out
template<int EPI>
__device__ __forceinline__ void hgemm_body(
    const __half* __restrict__ A, const __half* __restrict__ Wt,
    const float* __restrict__ bias, const float* __restrict__ resid,
    void* __restrict__ Cv, int K, int N)
{
    __shared__ __half As[2][128][40];   // [m][k], stride 40 halfs -> conflict-free
    __shared__ __half Bs[2][128][40];   // [n][k]

    const int tid  = threadIdx.x;
    const int wid  = tid >> 5;
    const int lane = tid & 31;
    const int lr   = lane >> 2;
    const int lc   = lane & 3;
    const int wm   = wid >> 2;
    const int wn   = wid & 3;

    const int rowBase = blockIdx.y * 128;
    const int colBase = blockIdx.x * 128;

    float acc[4][4][4];
    #pragma unroll
    for (int i = 0; i < 4; i++)
        #pragma unroll
        for (int j = 0; j < 4; j++)
            #pragma unroll
            for (int q = 0; q < 4; q++) acc[i][j][q] = 0.f;

    auto load_tiles = [&](int buf, int k0) {
        #pragma unroll
        for (int i = 0; i < 2; i++) {
            int c = tid + i * 256;          // 0..511
            int r = c >> 2, ko = (c & 3) * 8;
            cp_async16(&As[buf][r][ko], A  + (size_t)(rowBase + r) * K + k0 + ko);
            cp_async16(&Bs[buf][r][ko], Wt + (size_t)(colBase + r) * K + k0 + ko);
        }
    };

    const int niter = K >> 5;
    load_tiles(0, 0);
    CP_COMMIT();

    for (int it = 0; it < niter; it++) {
        const int buf = it & 1;
        if (it + 1 < niter) {
            load_tiles(buf ^ 1, (it + 1) << 5);
            CP_COMMIT();
            CP_WAIT(1);
        } else {
            CP_WAIT(0);
        }
        __syncthreads();

        #pragma unroll
        for (int kc = 0; kc < 2; kc++) {
            const int kk = kc * 16;
            uint32_t bf[4][2];
            #pragma unroll
            for (int j = 0; j < 4; j++) {
                const int n = wn * 32 + j * 8 + lr;
                bf[j][0] = *(const uint32_t*)&Bs[buf][n][kk + lc * 2];
                bf[j][1] = *(const uint32_t*)&Bs[buf][n][kk + 8 + lc * 2];
            }
            #pragma unroll
            for (int i = 0; i < 4; i++) {
                const int m = wm * 64 + i * 16;
                uint32_t a[4];
                a[0] = *(const uint32_t*)&As[buf][m + lr    ][kk + lc * 2];
                a[1] = *(const uint32_t*)&As[buf][m + 8 + lr][kk + lc * 2];
                a[2] = *(const uint32_t*)&As[buf][m + lr    ][kk + 8 + lc * 2];
                a[3] = *(const uint32_t*)&As[buf][m + 8 + lr][kk + 8 + lc * 2];
                #pragma unroll
                for (int j = 0; j < 4; j++) mma_f16(acc[i][j], a, bf[j][0], bf[j][1]);
            }
        }
        __syncthreads();
    }

    // epilogue
    const int row0 = rowBase + wm * 64;
    const int col0 = colBase + wn * 32;
    __half* Ch = (__half*)Cv;
    float*  Cf = (float*)Cv;
    #pragma unroll
    for (int j = 0; j < 4; j++) {
        const int col = col0 + j * 8 + lc * 2;
        const float b0v = bias[col], b1v = bias[col + 1];
        #pragma unroll
        for (int i = 0; i < 4; i++) {
            const int r0 = row0 + i * 16 + lr;
            float v0 = acc[i][j][0] + b0v;
            float v1 = acc[i][j][1] + b1v;
            float v2 = acc[i][j][2] + b0v;
            float v3 = acc[i][j][3] + b1v;
            if (EPI == 1) {
                v0 += resid[(size_t)r0 * N + col];
                v1 += resid[(size_t)r0 * N + col + 1];
                v2 += resid[(size_t)(r0 + 8) * N + col];
                v3 += resid[(size_t)(r0 + 8) * N + col + 1];
                *(float2*)&Cf[(size_t)r0 * N + col]       = make_float2(v0, v1);
                *(float2*)&Cf[(size_t)(r0 + 8) * N + col] = make_float2(v2, v3);
            } else {
                if (EPI == 2) {
                    v0 = gelu_exact(v0); v1 = gelu_exact(v1);
                    v2 = gelu_exact(v2); v3 = gelu_exact(v3);
                }
                *(__half2*)&Ch[(size_t)r0 * N + col]       = __floats2half2_rn(v0, v1);
                *(__half2*)&Ch[(size_t)(r0 + 8) * N + col] = __floats2half2_rn(v2, v3);
            }
        }
    }
}

template<int EPI>
__global__ void __launch_bounds__(256, 2)
hgemm(const __half* __restrict__ A, const __half* __restrict__ Wt,
      const float* __restrict__ bias, const float* __restrict__ resid,
      void* __restrict__ C, int K, int N)
{
    hgemm_body<EPI>(A, Wt, bias, resid, C, K, N);
}

__global__ void __launch_bounds__(256, 2)
hgemm_qkv(const __half* __restrict__ A,
          const __half* __restrict__ wq, const __half* __restrict__ wk, const __half* __restrict__ wv,
          const float* __restrict__ bq, const float* __restrict__ bk, const float* __restrict__ bv,
          __half* __restrict__ qo, __half* __restrict__ ko, __half* __restrict__ vo,
          int K, int N)
{
    const __half* W  = (blockIdx.z == 0) ? wq : (blockIdx.z == 1) ? wk : wv;
    const float*  bi = (blockIdx.z == 0) ? bq : (blockIdx.z == 1) ? bk : bv;
    __half*       C  = (blockIdx.z == 0) ? qo : (blockIdx.z == 1) ? ko : vo;
    hgemm_body<0>(A, W, bi, nullptr, C, K, N);
}

// ---------------- fp16 tensor-core causal flash attention ----------------
// grid (B*H, S/64), 128 threads (4 warps); warp owns 16 query rows.
// Q·K^T and P·V both m16n8k16 fp16. K/V tiles double-buffered via cp.async.
// V B-frags come from ldmatrix.x4.trans on the natural-layout V tile.
__global__ void __launch_bounds__(128)
attn_tc_kernel(const __half* __restrict__ q, const __half* __restrict__ k,
               const __half* __restrict__ v, __half* __restrict__ o)
{
    __shared__ __half Qs[64][72];        // stride 72 halfs (36 words) -> conflict-free
    __shared__ __half Ks[2][64][72];
    __shared__ __half Vs[2][64][72];

    const int bh   = blockIdx.x;
    const int b    = bh / HH;
    const int h    = bh % HH;
    const int T    = (gridDim.y - 1) - blockIdx.y;   // heavy tiles first
    const int q0   = T * 64;
    const int tid  = threadIdx.x;
    const int wid  = tid >> 5;
    const int lane = tid & 31;
    const int lr   = lane >> 2;
    const int lc   = lane & 3;
    const size_t headOff = (size_t)h * DKK;
    const size_t bBase   = (size_t)b * SS;

    auto loadKV = [&](int buf, int j0) {
        #pragma unroll
        for (int i = 0; i < 4; i++) {
            int c = tid + i * 128;              // 0..511
            int r = c >> 3, ko = (c & 7) * 8;
            cp_async16(&Ks[buf][r][ko], k + (bBase + j0 + r) * DD + headOff + ko);
            cp_async16(&Vs[buf][r][ko], v + (bBase + j0 + r) * DD + headOff + ko);
        }
    };

    // stage Q (plain vector loads) + kick off KV tile 0
    #pragma unroll
    for (int i = 0; i < 4; i++) {
        int c = tid + i * 128;                  // 0..511
        int r = c >> 3, ko = (c & 7) * 8;
        *(uint4*)&Qs[r][ko] = *(const uint4*)(q + (bBase + q0 + r) * DD + headOff + ko);
    }
    loadKV(0, 0);
    CP_COMMIT();
    __syncthreads();

    // register-resident Q A-frags, scaled by 1/8 (exact in fp16)
    const __half2 qscale = __half2half2(__float2half(0.125f));
    uint32_t qf[4][4];
    const int qrow = wid * 16;
    #pragma unroll
    for (int kc = 0; kc < 4; kc++) {
        const int kk = kc * 16;
        __half2 t0 = *(__half2*)&Qs[qrow + lr    ][kk + lc * 2];
        __half2 t1 = *(__half2*)&Qs[qrow + 8 + lr][kk + lc * 2];
        __half2 t2 = *(__half2*)&Qs[qrow + lr    ][kk + 8 + lc * 2];
        __half2 t3 = *(__half2*)&Qs[qrow + 8 + lr][kk + 8 + lc * 2];
        t0 = __hmul2(t0, qscale); t1 = __hmul2(t1, qscale);
        t2 = __hmul2(t2, qscale); t3 = __hmul2(t3, qscale);
        qf[kc][0] = *(uint32_t*)&t0; qf[kc][1] = *(uint32_t*)&t1;
        qf[kc][2] = *(uint32_t*)&t2; qf[kc][3] = *(uint32_t*)&t3;
    }

    // ldmatrix lane base offset into a V tile
    const int gq = lane >> 3, rr = lane & 7;
    const uint32_t vlane = ((uint32_t)(((gq & 1) * 8 + rr) * 72 + (gq >> 1) * 8)) * 2;
    uint32_t vbase[2];
    vbase[0] = (uint32_t)__cvta_generic_to_shared(&Vs[0][0][0]) + vlane;
    vbase[1] = (uint32_t)__cvta_generic_to_shared(&Vs[1][0][0]) + vlane;

    float oacc[8][4];
    #pragma unroll
    for (int nv = 0; nv < 8; nv++)
        #pragma unroll
        for (int t = 0; t < 4; t++) oacc[nv][t] = 0.f;
    float m0 = -1e30f, m1 = -1e30f, l0 = 0.f, l1 = 0.f;

    for (int kt = 0; kt <= T; kt++) {
        const int buf = kt & 1;
        if (kt < T) {
            loadKV(buf ^ 1, (kt + 1) * 64);
            CP_COMMIT();
            CP_WAIT(1);
        } else {
            CP_WAIT(0);
        }
        __syncthreads();

        // ---- S = Q K^T : 8 key n-tiles x 4 k16 chunks ----
        float sacc[8][4];
        #pragma unroll
        for (int nt = 0; nt < 8; nt++) {
            sacc[nt][0] = sacc[nt][1] = sacc[nt][2] = sacc[nt][3] = 0.f;
            #pragma unroll
            for (int kc = 0; kc < 4; kc++) {
                const int kk = kc * 16;
                uint32_t b0 = *(const uint32_t*)&Ks[buf][nt * 8 + lr][kk + lc * 2];
                uint32_t b1 = *(const uint32_t*)&Ks[buf][nt * 8 + lr][kk + 8 + lc * 2];
                mma_f16(sacc[nt], qf[kc], b0, b1);
            }
        }

        // ---- causal mask (diagonal tile only) ----
        if (kt == T) {
            const int qi0 = qrow + lr, qi1 = qi0 + 8;
            #pragma unroll
            for (int nt = 0; nt < 8; nt++) {
                const int kj = nt * 8 + lc * 2;
                if (kj     > qi0) sacc[nt][0] = -1e30f;
                if (kj + 1 > qi0) sacc[nt][1] = -1e30f;
                if (kj     > qi1) sacc[nt][2] = -1e30f;
                if (kj + 1 > qi1) sacc[nt][3] = -1e30f;
            }
        }

        // ---- online softmax ----
        float mx0 = -1e30f, mx1 = -1e30f;
        #pragma unroll
        for (int nt = 0; nt < 8; nt++) {
            mx0 = fmaxf(mx0, fmaxf(sacc[nt][0], sacc[nt][1]));
            mx1 = fmaxf(mx1, fmaxf(sacc[nt][2], sacc[nt][3]));
        }
        mx0 = fmaxf(mx0, __shfl_xor_sync(0xffffffffu, mx0, 1));
        mx0 = fmaxf(mx0, __shfl_xor_sync(0xffffffffu, mx0, 2));
        mx1 = fmaxf(mx1, __shfl_xor_sync(0xffffffffu, mx1, 1));
        mx1 = fmaxf(mx1, __shfl_xor_sync(0xffffffffu, mx1, 2));

        const float mn0 = fmaxf(m0, mx0);
        const float mn1 = fmaxf(m1, mx1);
        const float sc0 = __expf(m0 - mn0);
        const float sc1 = __expf(m1 - mn1);
        m0 = mn0; m1 = mn1;

        float la0 = 0.f, la1 = 0.f;
        #pragma unroll
        for (int nt = 0; nt < 8; nt++) {
            sacc[nt][0] = __expf(sacc[nt][0] - mn0);
            sacc[nt][1] = __expf(sacc[nt][1] - mn0);
            sacc[nt][2] = __expf(sacc[nt][2] - mn1);
            sacc[nt][3] = __expf(sacc[nt][3] - mn1);
            la0 += sacc[nt][0] + sacc[nt][1];
            la1 += sacc[nt][2] + sacc[nt][3];
        }
        la0 += __shfl_xor_sync(0xffffffffu, la0, 1);
        la0 += __shfl_xor_sync(0xffffffffu, la0, 2);
        la1 += __shfl_xor_sync(0xffffffffu, la1, 1);
        la1 += __shfl_xor_sync(0xffffffffu, la1, 2);
        l0 = l0 * sc0 + la0;
        l1 = l1 * sc1 + la1;

        #pragma unroll
        for (int nv = 0; nv < 8; nv++) {
            oacc[nv][0] *= sc0; oacc[nv][1] *= sc0;
            oacc[nv][2] *= sc1; oacc[nv][3] *= sc1;
        }

        // ---- pack P fragments (fp16) ----
        uint32_t pf[4][4];
        #pragma unroll
        for (int pk = 0; pk < 4; pk++) {
            __half2 h0 = __floats2half2_rn(sacc[2*pk    ][0], sacc[2*pk    ][1]);
            __half2 h1 = __floats2half2_rn(sacc[2*pk    ][2], sacc[2*pk    ][3]);
            __half2 h2 = __floats2half2_rn(sacc[2*pk + 1][0], sacc[2*pk + 1][1]);
            __half2 h3 = __floats2half2_rn(sacc[2*pk + 1][2], sacc[2*pk + 1][3]);
            pf[pk][0] = *(uint32_t*)&h0;
            pf[pk][1] = *(uint32_t*)&h1;
            pf[pk][2] = *(uint32_t*)&h2;
            pf[pk][3] = *(uint32_t*)&h3;
        }

        // ---- O += P V : ldmatrix.x4.trans gives B frags for two dk tiles ----
        #pragma unroll
        for (int nh = 0; nh < 4; nh++) {
            #pragma unroll
            for (int pk = 0; pk < 4; pk++) {
                uint32_t b0, b1, b2, b3;
                ldsm_x4_t(b0, b1, b2, b3, vbase[buf] + pk * 2304 + nh * 32);
                mma_f16(oacc[2*nh    ], pf[pk], b0, b1);
                mma_f16(oacc[2*nh + 1], pf[pk], b2, b3);
            }
        }
        __syncthreads();
    }

    // ---- normalize and write (half out) ----
    const float inv0 = 1.f / l0;
    const float inv1 = 1.f / l1;
    const size_t r0 = bBase + q0 + qrow + lr;
    #pragma unroll
    for (int nv = 0; nv < 8; nv++) {
        const int col = nv * 8 + lc * 2;
        *(__half2*)&o[r0 * DD + headOff + col] =
            __floats2half2_rn(oacc[nv][0] * inv0, oacc[nv][1] * inv0);
        *(__half2*)&o[(r0 + 8) * DD + headOff + col] =
            __floats2half2_rn(oacc[nv][2] * inv1, oacc[nv][3] * inv1);
    }
}

// ---------------- host launcher ----------------
extern "C" void kernel_launch(void* const* d_in, const int* in_sizes, int n_in,
                              void* d_out, int out_size)
{
    const float* x    = (const float*)d_in[0];
    const float* ln1g = (const float*)d_in[1];
    const float* ln1b = (const float*)d_in[2];
    const float* wq   = (const float*)d_in[3];
    const float* bq   = (const float*)d_in[4];
    const float* wk   = (const float*)d_in[5];
    const float* bk   = (const float*)d_in[6];
    const float* wv   = (const float*)d_in[7];
    const float* bv   = (const float*)d_in[8];
    const float* wo   = (const float*)d_in[9];
    const float* bo   = (const float*)d_in[10];
    const float* ln2g = (const float*)d_in[11];
    const float* ln2b = (const float*)d_in[12];
    const float* w1   = (const float*)d_in[13];
    const float* b1   = (const float*)d_in[14];
    const float* w2   = (const float*)d_in[15];
    const float* b2   = (const float*)d_in[16];
    float* out = (float*)d_out;

    __half *ln1, *qb, *kb, *vb, *attn, *ln2, *ffn1;
    __half *twq, *twk, *twv, *two, *tw1, *tw2;
    float *x1;
    cudaGetSymbolAddress((void**)&ln1,  h_ln1);
    cudaGetSymbolAddress((void**)&qb,   h_q);
    cudaGetSymbolAddress((void**)&kb,   h_k);
    cudaGetSymbolAddress((void**)&vb,   h_v);
    cudaGetSymbolAddress((void**)&attn, h_attn);
    cudaGetSymbolAddress((void**)&x1,   g_x1);
    cudaGetSymbolAddress((void**)&ln2,  h_ln2);
    cudaGetSymbolAddress((void**)&ffn1, h_ffn1);
    cudaGetSymbolAddress((void**)&twq,  h_wq);
    cudaGetSymbolAddress((void**)&twk,  h_wk);
    cudaGetSymbolAddress((void**)&twv,  h_wv);
    cudaGetSymbolAddress((void**)&two,  h_wo);
    cudaGetSymbolAddress((void**)&tw1,  h_w1);
    cudaGetSymbolAddress((void**)&tw2,  h_w2);

    // 0) weight transpose + convert (graph-replayed; deterministic)
    dim3 tb(32, 8);
    wconv_t<<<dim3(DD / 32, DD  / 32), tb>>>(wq, twq, DD,  DD);
    wconv_t<<<dim3(DD / 32, DD  / 32), tb>>>(wk, twk, DD,  DD);
    wconv_t<<<dim3(DD / 32, DD  / 32), tb>>>(wv, twv, DD,  DD);
    wconv_t<<<dim3(DD / 32, DD  / 32), tb>>>(wo, two, DD,  DD);
    wconv_t<<<dim3(DD / 32, DFF / 32), tb>>>(w1, tw1, DD,  DFF);
    wconv_t<<<dim3(DFF / 32, DD / 32), tb>>>(w2, tw2, DFF, DD);

    // 1) LN1 -> half
    ln_kernel<<<MROWS, 256>>>(x, ln1g, ln1b, ln1);

    // 2) QKV projections (fp16 tensor cores)
    hgemm_qkv<<<dim3(DD / 128, MROWS / 128, 3), 256>>>(
        ln1, twq, twk, twv, bq, bk, bv, qb, kb, vb, DD, DD);

    // 3) causal attention (fp16 tensor cores, double-buffered)
    attn_tc_kernel<<<dim3(BB * HH, SS / 64), 128>>>(qb, kb, vb, attn);

    // 4) O projection + residual -> f32 x1
    hgemm<1><<<dim3(DD / 128, MROWS / 128), 256>>>(attn, two, bo, x, x1, DD, DD);

    // 5) LN2 -> half
    ln_kernel<<<MROWS, 256>>>(x1, ln2g, ln2b, ln2);

    // 6) FFN up + GELU -> half
    hgemm<2><<<dim3(DFF / 128, MROWS / 128), 256>>>(ln2, tw1, b1, nullptr, ffn1, DD, DFF);

    // 7) FFN down + residual -> f32 out
    hgemm<1><<<dim3(DD / 128, MROWS / 128), 256>>>(ffn1, tw2, b2, x1, out, DFF, DD);
}

// round 6
// speedup vs baseline: 6.2529x; 1.0850x over previous
#include <cuda_runtime.h>
#include <cuda_fp16.h>
#include <math.h>
#include <stdint.h>

#define BB 2
#define SS 2048
#define DD 768
#define HH 12
#define DKK 64
#define DFF 3072
#define MROWS (BB*SS)   // 4096

// ---------------- scratch (device globals: allocation-free) ----------------
__device__ __half h_ln1 [MROWS*DD];
__device__ __half h_q   [MROWS*DD];
__device__ __half h_k   [MROWS*DD];
__device__ __half h_v   [MROWS*DD];
__device__ __half h_attn[MROWS*DD];
__device__ float  g_x1  [MROWS*DD];
__device__ __half h_ln2 [MROWS*DD];
__device__ __half h_ffn1[MROWS*DFF];
// transposed half weights: Wt[N][K]
__device__ __half h_wq[DD*DD];
__device__ __half h_wk[DD*DD];
__device__ __half h_wv[DD*DD];
__device__ __half h_wo[DD*DD];
__device__ __half h_w1[DD*DFF];
__device__ __half h_w2[DFF*DD];

// ---------------- helpers ----------------
__device__ __forceinline__ float gelu_exact(float v) {
    return 0.5f * v * (1.0f + erff(v * 0.70710678118654752f));
}
__device__ __forceinline__ void cp_async16(void* smem, const void* gmem) {
    uint32_t s = (uint32_t)__cvta_generic_to_shared(smem);
    asm volatile("cp.async.cg.shared.global [%0], [%1], 16;\n" :: "r"(s), "l"(gmem));
}
#define CP_COMMIT() asm volatile("cp.async.commit_group;\n" ::)
#define CP_WAIT(n)  asm volatile("cp.async.wait_group %0;\n" :: "n"(n))

__device__ __forceinline__ void mma_f16(float* c, const uint32_t* a, uint32_t b0, uint32_t b1) {
    asm volatile(
      "mma.sync.aligned.m16n8k16.row.col.f32.f16.f16.f32 "
      "{%0,%1,%2,%3}, {%4,%5,%6,%7}, {%8,%9}, {%0,%1,%2,%3};\n"
      : "+f"(c[0]), "+f"(c[1]), "+f"(c[2]), "+f"(c[3])
      : "r"(a[0]), "r"(a[1]), "r"(a[2]), "r"(a[3]), "r"(b0), "r"(b1));
}
__device__ __forceinline__ void ldsm_x4(uint32_t& r0, uint32_t& r1, uint32_t& r2, uint32_t& r3,
                                        uint32_t addr) {
    asm volatile("ldmatrix.sync.aligned.m8n8.x4.shared.b16 {%0,%1,%2,%3}, [%4];\n"
      : "=r"(r0), "=r"(r1), "=r"(r2), "=r"(r3) : "r"(addr));
}
__device__ __forceinline__ void ldsm_x4_t(uint32_t& r0, uint32_t& r1, uint32_t& r2, uint32_t& r3,
                                          uint32_t addr) {
    asm volatile("ldmatrix.sync.aligned.m8n8.x4.trans.shared.b16 {%0,%1,%2,%3}, [%4];\n"
      : "=r"(r0), "=r"(r1), "=r"(r2), "=r"(r3) : "r"(addr));
}

// ---------------- fused weight transpose + f32->f16 convert ----------------
// One launch for all six weights. Wt[n][k] = (half) W[k][n], 32x32 tiles.
__global__ void wconv_all(const float* __restrict__ wq, const float* __restrict__ wk,
                          const float* __restrict__ wv, const float* __restrict__ wo,
                          const float* __restrict__ w1, const float* __restrict__ w2,
                          __half* __restrict__ twq, __half* __restrict__ twk,
                          __half* __restrict__ twv, __half* __restrict__ two,
                          __half* __restrict__ tw1, __half* __restrict__ tw2)
{
    const int idx = blockIdx.x;
    const float* W; __half* Wt; int K, N, tk, tn;
    if (idx < 2304) {                          // 4 square weights, 576 tiles each
        const int which = idx / 576, r = idx % 576;
        W  = (which == 0) ? wq  : (which == 1) ? wk  : (which == 2) ? wv  : wo;
        Wt = (which == 0) ? twq : (which == 1) ? twk : (which == 2) ? twv : two;
        K = DD; N = DD; tk = r % 24; tn = r / 24;
    } else if (idx < 4608) {                   // w1: K=DD, N=DFF (24 x 96 tiles)
        const int r = idx - 2304;
        W = w1; Wt = tw1; K = DD; N = DFF; tk = r % 24; tn = r / 24;
    } else {                                   // w2: K=DFF, N=DD (96 x 24 tiles)
        const int r = idx - 4608;
        W = w2; Wt = tw2; K = DFF; N = DD; tk = r % 96; tn = r / 96;
    }
    __shared__ float t[32][33];
    const int k0 = tk * 32, n0 = tn * 32;
    const int tx = threadIdx.x, ty = threadIdx.y;   // 32 x 8
    #pragma unroll
    for (int i = 0; i < 32; i += 8)
        t[ty + i][tx] = W[(size_t)(k0 + ty + i) * N + n0 + tx];
    __syncthreads();
    #pragma unroll
    for (int i = 0; i < 32; i += 8)
        Wt[(size_t)(n0 + ty + i) * K + k0 + tx] = __float2half_rn(t[tx][ty + i]);
}

// ---------------- LayerNorm: f32 in, f16 out ----------------
__global__ void ln_kernel(const float* __restrict__ x,
                          const float* __restrict__ gamma,
                          const float* __restrict__ beta,
                          __half* __restrict__ out)
{
    int row = blockIdx.x;
    const float* xr = x + (size_t)row * DD;
    int tid = threadIdx.x;

    float a = xr[tid], b = xr[tid + 256], c = xr[tid + 512];
    float s  = a + b + c;
    float ss = a*a + b*b + c*c;
    #pragma unroll
    for (int off = 16; off > 0; off >>= 1) {
        s  += __shfl_xor_sync(0xffffffffu, s,  off);
        ss += __shfl_xor_sync(0xffffffffu, ss, off);
    }
    __shared__ float sh0[8], sh1[8];
    int wid = tid >> 5, lane = tid & 31;
    if (lane == 0) { sh0[wid] = s; sh1[wid] = ss; }
    __syncthreads();
    float tot = 0.f, tot2 = 0.f;
    #pragma unroll
    for (int i = 0; i < 8; i++) { tot += sh0[i]; tot2 += sh1[i]; }
    float mean = tot * (1.0f / DD);
    float var  = tot2 * (1.0f / DD) - mean * mean;
    float rstd = rsqrtf(var + 1e-7f);

    __half* orow = out + (size_t)row * DD;
    orow[tid      ] = __float2half_rn(gamma[tid      ] * (a - mean) * rstd + beta[tid      ]);
    orow[tid + 256] = __float2half_rn(gamma[tid + 256] * (b - mean) * rstd + beta[tid + 256]);
    orow[tid + 512] = __float2half_rn(gamma[tid + 512] * (c - mean) * rstd + beta[tid + 512]);
}

// ---------------- fp16 tensor-core GEMM (ldmatrix fragment loads) ----------------
// C[M,N] = A[M,K](f16) @ Wt[N,K](f16)^T + bias(f32)
// BM=BN=128, BK=32, 256 threads, warps 2x4, warp tile 64x32, m16n8k16.
// EPI: 0 = bias -> half | 1 = bias + resid -> f32 | 2 = bias + GELU -> half
template<int EPI>
__device__ __forceinline__ void hgemm_body(
    const __half* __restrict__ A, const __half* __restrict__ Wt,
    const float* __restrict__ bias, const float* __restrict__ resid,
    void* __restrict__ Cv, int K, int N)
{
    __shared__ __half As[2][128][40];
    __shared__ __half Bs[2][128][40];

    const int tid  = threadIdx.x;
    const int wid  = tid >> 5;
    const int lane = tid & 31;
    const int lr   = lane >> 2;
    const int lc   = lane & 3;
    const int wm   = wid >> 2;
    const int wn   = wid & 3;

    const int rowBase = blockIdx.y * 128;
    const int colBase = blockIdx.x * 128;

    float acc[4][4][4];
    #pragma unroll
    for (int i = 0; i < 4; i++)
        #pragma unroll
        for (int j = 0; j < 4; j++)
            #pragma unroll
            for (int q = 0; q < 4; q++) acc[i][j][q] = 0.f;

    auto load_tiles = [&](int buf, int k0) {
        #pragma unroll
        for (int i = 0; i < 2; i++) {
            int c = tid + i * 256;          // 0..511
            int r = c >> 2, ko = (c & 3) * 8;
            cp_async16(&As[buf][r][ko], A  + (size_t)(rowBase + r) * K + k0 + ko);
            cp_async16(&Bs[buf][r][ko], Wt + (size_t)(colBase + r) * K + k0 + ko);
        }
    };

    // ldmatrix lane addressing (in halfs): A x4 and B x4
    const int g = lane >> 3;                 // matrix index 0..3
    const int grow = lane & 7;               // row within matrix
    const int aRowOff = ((g & 1) * 8 + grow);       // + m
    const int aColOff = (g >> 1) * 8;               // + kk
    const int bRowOff = ((g >> 1) * 8 + grow);      // + n0 (jp*16)
    const int bColOff = (g & 1) * 8;                // + kk

    const int niter = K >> 5;
    load_tiles(0, 0);
    CP_COMMIT();

    for (int it = 0; it < niter; it++) {
        const int buf = it & 1;
        if (it + 1 < niter) {
            load_tiles(buf ^ 1, (it + 1) << 5);
            CP_COMMIT();
            CP_WAIT(1);
        } else {
            CP_WAIT(0);
        }
        __syncthreads();

        #pragma unroll
        for (int kc = 0; kc < 2; kc++) {
            const int kk = kc * 16;
            uint32_t bf[4][2];
            #pragma unroll
            for (int jp = 0; jp < 2; jp++) {
                const int n = wn * 32 + jp * 16 + bRowOff;
                uint32_t addr = (uint32_t)__cvta_generic_to_shared(&Bs[buf][n][kk + bColOff]);
                ldsm_x4(bf[2*jp][0], bf[2*jp][1], bf[2*jp+1][0], bf[2*jp+1][1], addr);
            }
            #pragma unroll
            for (int i = 0; i < 4; i++) {
                const int m = wm * 64 + i * 16;
                uint32_t a[4];
                uint32_t addr = (uint32_t)__cvta_generic_to_shared(&As[buf][m + aRowOff][kk + aColOff]);
                ldsm_x4(a[0], a[1], a[2], a[3], addr);
                #pragma unroll
                for (int j = 0; j < 4; j++) mma_f16(acc[i][j], a, bf[j][0], bf[j][1]);
            }
        }
        __syncthreads();
    }

    // epilogue
    const int row0 = rowBase + wm * 64;
    const int col0 = colBase + wn * 32;
    __half* Ch = (__half*)Cv;
    float*  Cf = (float*)Cv;
    #pragma unroll
    for (int j = 0; j < 4; j++) {
        const int col = col0 + j * 8 + lc * 2;
        const float b0v = bias[col], b1v = bias[col + 1];
        #pragma unroll
        for (int i = 0; i < 4; i++) {
            const int r0 = row0 + i * 16 + lr;
            float v0 = acc[i][j][0] + b0v;
            float v1 = acc[i][j][1] + b1v;
            float v2 = acc[i][j][2] + b0v;
            float v3 = acc[i][j][3] + b1v;
            if (EPI == 1) {
                v0 += resid[(size_t)r0 * N + col];
                v1 += resid[(size_t)r0 * N + col + 1];
                v2 += resid[(size_t)(r0 + 8) * N + col];
                v3 += resid[(size_t)(r0 + 8) * N + col + 1];
                *(float2*)&Cf[(size_t)r0 * N + col]       = make_float2(v0, v1);
                *(float2*)&Cf[(size_t)(r0 + 8) * N + col] = make_float2(v2, v3);
            } else {
                if (EPI == 2) {
                    v0 = gelu_exact(v0); v1 = gelu_exact(v1);
                    v2 = gelu_exact(v2); v3 = gelu_exact(v3);
                }
                *(__half2*)&Ch[(size_t)r0 * N + col]       = __floats2half2_rn(v0, v1);
                *(__half2*)&Ch[(size_t)(r0 + 8) * N + col] = __floats2half2_rn(v2, v3);
            }
        }
    }
}

template<int EPI>
__global__ void __launch_bounds__(256, 2)
hgemm(const __half* __restrict__ A, const __half* __restrict__ Wt,
      const float* __restrict__ bias, const float* __restrict__ resid,
      void* __restrict__ C, int K, int N)
{
    hgemm_body<EPI>(A, Wt, bias, resid, C, K, N);
}

__global__ void __launch_bounds__(256, 2)
hgemm_qkv(const __half* __restrict__ A,
          const __half* __restrict__ wq, const __half* __restrict__ wk, const __half* __restrict__ wv,
          const float* __restrict__ bq, const float* __restrict__ bk, const float* __restrict__ bv,
          __half* __restrict__ qo, __half* __restrict__ ko, __half* __restrict__ vo,
          int K, int N)
{
    const __half* W  = (blockIdx.z == 0) ? wq : (blockIdx.z == 1) ? wk : wv;
    const float*  bi = (blockIdx.z == 0) ? bq : (blockIdx.z == 1) ? bk : bv;
    __half*       C  = (blockIdx.z == 0) ? qo : (blockIdx.z == 1) ? ko : vo;
    hgemm_body<0>(A, W, bi, nullptr, C, K, N);
}

// ---------------- fp16 tensor-core causal flash attention ----------------
// grid (B*H, S/128), 256 threads (8 warps); each warp owns 16 query rows.
// KV double-buffered; Q staging overlays KV smem (used before first KV write).
// Fully-masked key tiles are skipped per-warp.
__global__ void __launch_bounds__(256)
attn_tc_kernel(const __half* __restrict__ q, const __half* __restrict__ k,
               const __half* __restrict__ v, __half* __restrict__ o)
{
    __shared__ __half sm[2][2][64][72];   // [buf][0=K,1=V][row][col], 36,864 B

    const int bh   = blockIdx.x;
    const int b    = bh / HH;
    const int h    = bh % HH;
    const int T    = (gridDim.y - 1) - blockIdx.y;   // heavy tiles first
    const int q0   = T * 128;
    const int tid  = threadIdx.x;
    const int wid  = tid >> 5;
    const int lane = tid & 31;
    const int lr   = lane >> 2;
    const int lc   = lane & 3;
    const size_t headOff = (size_t)h * DKK;
    const size_t bBase   = (size_t)b * SS;

    // ---- stage Q into overlay region (first 18 KB of sm), extract frags ----
    {
        __half* Qst = &sm[0][0][0][0];   // 128 rows x stride 72
        #pragma unroll
        for (int i = 0; i < 4; i++) {
            int c = tid + i * 256;                   // 0..1023
            int r = c >> 3, ko = (c & 7) * 8;
            *(uint4*)&Qst[r * 72 + ko] = *(const uint4*)(q + (bBase + q0 + r) * DD + headOff + ko);
        }
    }
    __syncthreads();

    const __half2 qscale = __half2half2(__float2half(0.125f));   // 1/sqrt(64), exact
    uint32_t qf[4][4];
    const int qrow = wid * 16;
    {
        const __half* Qst = &sm[0][0][0][0];
        #pragma unroll
        for (int kc = 0; kc < 4; kc++) {
            const int kk = kc * 16;
            __half2 t0 = *(__half2*)&Qst[(qrow + lr    ) * 72 + kk + lc * 2];
            __half2 t1 = *(__half2*)&Qst[(qrow + 8 + lr) * 72 + kk + lc * 2];
            __half2 t2 = *(__half2*)&Qst[(qrow + lr    ) * 72 + kk + 8 + lc * 2];
            __half2 t3 = *(__half2*)&Qst[(qrow + 8 + lr) * 72 + kk + 8 + lc * 2];
            t0 = __hmul2(t0, qscale); t1 = __hmul2(t1, qscale);
            t2 = __hmul2(t2, qscale); t3 = __hmul2(t3, qscale);
            qf[kc][0] = *(uint32_t*)&t0; qf[kc][1] = *(uint32_t*)&t1;
            qf[kc][2] = *(uint32_t*)&t2; qf[kc][3] = *(uint32_t*)&t3;
        }
    }
    __syncthreads();   // Q reads done before KV overwrites the overlay

    auto loadKV = [&](int buf, int j0) {
        #pragma unroll
        for (int i = 0; i < 2; i++) {
            int c = tid + i * 256;                   // 0..511
            int r = c >> 3, ko = (c & 7) * 8;
            cp_async16(&sm[buf][0][r][ko], k + (bBase + j0 + r) * DD + headOff + ko);
            cp_async16(&sm[buf][1][r][ko], v + (bBase + j0 + r) * DD + headOff + ko);
        }
    };

    // ldmatrix.trans lane base offset into a V tile (bytes)
    const int gq = lane >> 3, rr = lane & 7;
    const uint32_t vlane = ((uint32_t)(((gq & 1) * 8 + rr) * 72 + (gq >> 1) * 8)) * 2;
    uint32_t vbase[2];
    vbase[0] = (uint32_t)__cvta_generic_to_shared(&sm[0][1][0][0]) + vlane;
    vbase[1] = (uint32_t)__cvta_generic_to_shared(&sm[1][1][0][0]) + vlane;

    float oacc[8][4];
    #pragma unroll
    for (int nv = 0; nv < 8; nv++)
        #pragma unroll
        for (int t = 0; t < 4; t++) oacc[nv][t] = 0.f;
    float m0 = -1e30f, m1 = -1e30f, l0 = 0.f, l1 = 0.f;

    const int qglob0 = q0 + qrow;          // first query row of this warp
    const int nkt = 2 * T + 2;             // key tiles covering [0, q0+128)

    loadKV(0, 0);
    CP_COMMIT();

    for (int kt = 0; kt < nkt; kt++) {
        const int buf = kt & 1;
        const int j0 = kt * 64;
        if (kt + 1 < nkt) {
            loadKV(buf ^ 1, (kt + 1) * 64);
            CP_COMMIT();
            CP_WAIT(1);
        } else {
            CP_WAIT(0);
        }
        __syncthreads();

        if (j0 <= qglob0 + 15) {           // else: fully masked for this warp -> skip
            // ---- S = Q K^T : 8 key n-tiles x 4 k16 chunks ----
            float sacc[8][4];
            #pragma unroll
            for (int nt = 0; nt < 8; nt++) {
                sacc[nt][0] = sacc[nt][1] = sacc[nt][2] = sacc[nt][3] = 0.f;
                #pragma unroll
                for (int kc = 0; kc < 4; kc++) {
                    const int kk = kc * 16;
                    uint32_t b0 = *(const uint32_t*)&sm[buf][0][nt * 8 + lr][kk + lc * 2];
                    uint32_t b1 = *(const uint32_t*)&sm[buf][0][nt * 8 + lr][kk + 8 + lc * 2];
                    mma_f16(sacc[nt], qf[kc], b0, b1);
                }
            }

            // ---- causal mask (diagonal tiles only) ----
            if (j0 + 63 > qglob0) {
                const int qi0 = qglob0 + lr, qi1 = qi0 + 8;
                #pragma unroll
                for (int nt = 0; nt < 8; nt++) {
                    const int kj = j0 + nt * 8 + lc * 2;
                    if (kj     > qi0) sacc[nt][0] = -1e30f;
                    if (kj + 1 > qi0) sacc[nt][1] = -1e30f;
                    if (kj     > qi1) sacc[nt][2] = -1e30f;
                    if (kj + 1 > qi1) sacc[nt][3] = -1e30f;
                }
            }

            // ---- online softmax ----
            float mx0 = -1e30f, mx1 = -1e30f;
            #pragma unroll
            for (int nt = 0; nt < 8; nt++) {
                mx0 = fmaxf(mx0, fmaxf(sacc[nt][0], sacc[nt][1]));
                mx1 = fmaxf(mx1, fmaxf(sacc[nt][2], sacc[nt][3]));
            }
            mx0 = fmaxf(mx0, __shfl_xor_sync(0xffffffffu, mx0, 1));
            mx0 = fmaxf(mx0, __shfl_xor_sync(0xffffffffu, mx0, 2));
            mx1 = fmaxf(mx1, __shfl_xor_sync(0xffffffffu, mx1, 1));
            mx1 = fmaxf(mx1, __shfl_xor_sync(0xffffffffu, mx1, 2));

            const float mn0 = fmaxf(m0, mx0);
            const float mn1 = fmaxf(m1, mx1);
            const float sc0 = __expf(m0 - mn0);
            const float sc1 = __expf(m1 - mn1);
            m0 = mn0; m1 = mn1;

            float la0 = 0.f, la1 = 0.f;
            #pragma unroll
            for (int nt = 0; nt < 8; nt++) {
                sacc[nt][0] = __expf(sacc[nt][0] - mn0);
                sacc[nt][1] = __expf(sacc[nt][1] - mn0);
                sacc[nt][2] = __expf(sacc[nt][2] - mn1);
                sacc[nt][3] = __expf(sacc[nt][3] - mn1);
                la0 += sacc[nt][0] + sacc[nt][1];
                la1 += sacc[nt][2] + sacc[nt][3];
            }
            la0 += __shfl_xor_sync(0xffffffffu, la0, 1);
            la0 += __shfl_xor_sync(0xffffffffu, la0, 2);
            la1 += __shfl_xor_sync(0xffffffffu, la1, 1);
            la1 += __shfl_xor_sync(0xffffffffu, la1, 2);
            l0 = l0 * sc0 + la0;
            l1 = l1 * sc1 + la1;

            #pragma unroll
            for (int nv = 0; nv < 8; nv++) {
                oacc[nv][0] *= sc0; oacc[nv][1] *= sc0;
                oacc[nv][2] *= sc1; oacc[nv][3] *= sc1;
            }

            // ---- pack P fragments (fp16) ----
            uint32_t pf[4][4];
            #pragma unroll
            for (int pk = 0; pk < 4; pk++) {
                __half2 h0 = __floats2half2_rn(sacc[2*pk    ][0], sacc[2*pk    ][1]);
                __half2 h1 = __floats2half2_rn(sacc[2*pk    ][2], sacc[2*pk    ][3]);
                __half2 h2 = __floats2half2_rn(sacc[2*pk + 1][0], sacc[2*pk + 1][1]);
                __half2 h3 = __floats2half2_rn(sacc[2*pk + 1][2], sacc[2*pk + 1][3]);
                pf[pk][0] = *(uint32_t*)&h0;
                pf[pk][1] = *(uint32_t*)&h1;
                pf[pk][2] = *(uint32_t*)&h2;
                pf[pk][3] = *(uint32_t*)&h3;
            }

            // ---- O += P V (ldmatrix.x4.trans on natural-layout V) ----
            #pragma unroll
            for (int nh = 0; nh < 4; nh++) {
                #pragma unroll
                for (int pk = 0; pk < 4; pk++) {
                    uint32_t b0, b1, b2, b3;
                    ldsm_x4_t(b0, b1, b2, b3, vbase[buf] + pk * 2304 + nh * 32);
                    mma_f16(oacc[2*nh    ], pf[pk], b0, b1);
                    mma_f16(oacc[2*nh + 1], pf[pk], b2, b3);
                }
            }
        }
        __syncthreads();
    }

    // ---- normalize and write (half out) ----
    const float inv0 = 1.f / l0;
    const float inv1 = 1.f / l1;
    const size_t r0 = bBase + q0 + qrow + lr;
    #pragma unroll
    for (int nv = 0; nv < 8; nv++) {
        const int col = nv * 8 + lc * 2;
        *(__half2*)&o[r0 * DD + headOff + col] =
            __floats2half2_rn(oacc[nv][0] * inv0, oacc[nv][1] * inv0);
        *(__half2*)&o[(r0 + 8) * DD + headOff + col] =
            __floats2half2_rn(oacc[nv][2] * inv1, oacc[nv][3] * inv1);
    }
}

// ---------------- host launcher ----------------
extern "C" void kernel_launch(void* const* d_in, const int* in_sizes, int n_in,
                              void* d_out, int out_size)
{
    const float* x    = (const float*)d_in[0];
    const float* ln1g = (const float*)d_in[1];
    const float* ln1b = (const float*)d_in[2];
    const float* wq   = (const float*)d_in[3];
    const float* bq   = (const float*)d_in[4];
    const float* wk   = (const float*)d_in[5];
    const float* bk   = (const float*)d_in[6];
    const float* wv   = (const float*)d_in[7];
    const float* bv   = (const float*)d_in[8];
    const float* wo   = (const float*)d_in[9];
    const float* bo   = (const float*)d_in[10];
    const float* ln2g = (const float*)d_in[11];
    const float* ln2b = (const float*)d_in[12];
    const float* w1   = (const float*)d_in[13];
    const float* b1   = (const float*)d_in[14];
    const float* w2   = (const float*)d_in[15];
    const float* b2   = (const float*)d_in[16];
    float* out = (float*)d_out;

    __half *ln1, *qb, *kb, *vb, *attn, *ln2, *ffn1;
    __half *twq, *twk, *twv, *two, *tw1, *tw2;
    float *x1;
    cudaGetSymbolAddress((void**)&ln1,  h_ln1);
    cudaGetSymbolAddress((void**)&qb,   h_q);
    cudaGetSymbolAddress((void**)&kb,   h_k);
    cudaGetSymbolAddress((void**)&vb,   h_v);
    cudaGetSymbolAddress((void**)&attn, h_attn);
    cudaGetSymbolAddress((void**)&x1,   g_x1);
    cudaGetSymbolAddress((void**)&ln2,  h_ln2);
    cudaGetSymbolAddress((void**)&ffn1, h_ffn1);
    cudaGetSymbolAddress((void**)&twq,  h_wq);
    cudaGetSymbolAddress((void**)&twk,  h_wk);
    cudaGetSymbolAddress((void**)&twv,  h_wv);
    cudaGetSymbolAddress((void**)&two,  h_wo);
    cudaGetSymbolAddress((void**)&tw1,  h_w1);
    cudaGetSymbolAddress((void**)&tw2,  h_w2);

    // 0) all weight converts in one launch
    wconv_all<<<6912, dim3(32, 8)>>>(wq, wk, wv, wo, w1, w2,
                                     twq, twk, twv, two, tw1, tw2);

    // 1) LN1 -> half
    ln_kernel<<<MROWS, 256>>>(x, ln1g, ln1b, ln1);

    // 2) QKV projections
    hgemm_qkv<<<dim3(DD / 128, MROWS / 128, 3), 256>>>(
        ln1, twq, twk, twv, bq, bk, bv, qb, kb, vb, DD, DD);

    // 3) causal attention (128-query tiles, 8 warps)
    attn_tc_kernel<<<dim3(BB * HH, SS / 128), 256>>>(qb, kb, vb, attn);

    // 4) O projection + residual -> f32 x1
    hgemm<1><<<dim3(DD / 128, MROWS / 128), 256>>>(attn, two, bo, x, x1, DD, DD);

    // 5) LN2 -> half
    ln_kernel<<<MROWS, 256>>>(x1, ln2g, ln2b, ln2);

    // 6) FFN up + GELU -> half
    hgemm<2><<<dim3(DFF / 128, MROWS / 128), 256>>>(ln2, tw1, b1, nullptr, ffn1, DD, DFF);

    // 7) FFN down + residual -> f32 out
    hgemm<1><<<dim3(DD / 128, MROWS / 128), 256>>>(ffn1, tw2, b2, x1, out, DFF, DD);
}

// round 8
// speedup vs baseline: 7.1673x; 1.1462x over previous
#include <cuda_runtime.h>
#include <cuda_fp16.h>
#include <math.h>
#include <stdint.h>

#define BB 2
#define SS 2048
#define DD 768
#define HH 12
#define DKK 64
#define DFF 3072
#define MROWS (BB*SS)   // 4096

// ---------------- scratch (device globals: allocation-free) ----------------
__device__ __half h_ln1 [MROWS*DD];
__device__ __half h_q   [MROWS*DD];
__device__ __half h_k   [MROWS*DD];
__device__ __half h_v   [MROWS*DD];
__device__ __half h_attn[MROWS*DD];
__device__ float  g_x1  [MROWS*DD];
__device__ __half h_ln2 [MROWS*DD];
__device__ __half h_ffn1[MROWS*DFF];
// transposed half weights: Wt[N][K]
__device__ __half h_wq[DD*DD];
__device__ __half h_wk[DD*DD];
__device__ __half h_wv[DD*DD];
__device__ __half h_wo[DD*DD];
__device__ __half h_w1[DD*DFF];
__device__ __half h_w2[DFF*DD];

// ---------------- helpers ----------------
__device__ __forceinline__ float gelu_exact(float v) {
    return 0.5f * v * (1.0f + erff(v * 0.70710678118654752f));
}
__device__ __forceinline__ void cp_async16(void* smem, const void* gmem) {
    uint32_t s = (uint32_t)__cvta_generic_to_shared(smem);
    asm volatile("cp.async.cg.shared.global [%0], [%1], 16;\n" :: "r"(s), "l"(gmem));
}
#define CP_COMMIT() asm volatile("cp.async.commit_group;\n" ::)
#define CP_WAIT(n)  asm volatile("cp.async.wait_group %0;\n" :: "n"(n))

__device__ __forceinline__ void mma_f16(float* c, const uint32_t* a, uint32_t b0, uint32_t b1) {
    asm volatile(
      "mma.sync.aligned.m16n8k16.row.col.f32.f16.f16.f32 "
      "{%0,%1,%2,%3}, {%4,%5,%6,%7}, {%8,%9}, {%0,%1,%2,%3};\n"
      : "+f"(c[0]), "+f"(c[1]), "+f"(c[2]), "+f"(c[3])
      : "r"(a[0]), "r"(a[1]), "r"(a[2]), "r"(a[3]), "r"(b0), "r"(b1));
}
__device__ __forceinline__ void ldsm_x4(uint32_t& r0, uint32_t& r1, uint32_t& r2, uint32_t& r3,
                                        uint32_t addr) {
    asm volatile("ldmatrix.sync.aligned.m8n8.x4.shared.b16 {%0,%1,%2,%3}, [%4];\n"
      : "=r"(r0), "=r"(r1), "=r"(r2), "=r"(r3) : "r"(addr));
}
__device__ __forceinline__ void ldsm_x4_t(uint32_t& r0, uint32_t& r1, uint32_t& r2, uint32_t& r3,
                                          uint32_t addr) {
    asm volatile("ldmatrix.sync.aligned.m8n8.x4.trans.shared.b16 {%0,%1,%2,%3}, [%4];\n"
      : "=r"(r0), "=r"(r1), "=r"(r2), "=r"(r3) : "r"(addr));
}

// ---------------- fused weight transpose + f32->f16 convert ----------------
__global__ void wconv_all(const float* __restrict__ wq, const float* __restrict__ wk,
                          const float* __restrict__ wv, const float* __restrict__ wo,
                          const float* __restrict__ w1, const float* __restrict__ w2,
                          __half* __restrict__ twq, __half* __restrict__ twk,
                          __half* __restrict__ twv, __half* __restrict__ two,
                          __half* __restrict__ tw1, __half* __restrict__ tw2)
{
    const int idx = blockIdx.x;
    const float* W; __half* Wt; int K, N, tk, tn;
    if (idx < 2304) {
        const int which = idx / 576, r = idx % 576;
        W  = (which == 0) ? wq  : (which == 1) ? wk  : (which == 2) ? wv  : wo;
        Wt = (which == 0) ? twq : (which == 1) ? twk : (which == 2) ? twv : two;
        K = DD; N = DD; tk = r % 24; tn = r / 24;
    } else if (idx < 4608) {
        const int r = idx - 2304;
        W = w1; Wt = tw1; K = DD; N = DFF; tk = r % 24; tn = r / 24;
    } else {
        const int r = idx - 4608;
        W = w2; Wt = tw2; K = DFF; N = DD; tk = r % 96; tn = r / 96;
    }
    __shared__ float t[32][33];
    const int k0 = tk * 32, n0 = tn * 32;
    const int tx = threadIdx.x, ty = threadIdx.y;
    #pragma unroll
    for (int i = 0; i < 32; i += 8)
        t[ty + i][tx] = W[(size_t)(k0 + ty + i) * N + n0 + tx];
    __syncthreads();
    #pragma unroll
    for (int i = 0; i < 32; i += 8)
        Wt[(size_t)(n0 + ty + i) * K + k0 + tx] = __float2half_rn(t[tx][ty + i]);
}

// ---------------- LayerNorm: f32 in, f16 out ----------------
__global__ void ln_kernel(const float* __restrict__ x,
                          const float* __restrict__ gamma,
                          const float* __restrict__ beta,
                          __half* __restrict__ out)
{
    int row = blockIdx.x;
    const float* xr = x + (size_t)row * DD;
    int tid = threadIdx.x;

    float a = xr[tid], b = xr[tid + 256], c = xr[tid + 512];
    float s  = a + b + c;
    float ss = a*a + b*b + c*c;
    #pragma unroll
    for (int off = 16; off > 0; off >>= 1) {
        s  += __shfl_xor_sync(0xffffffffu, s,  off);
        ss += __shfl_xor_sync(0xffffffffu, ss, off);
    }
    __shared__ float sh0[8], sh1[8];
    int wid = tid >> 5, lane = tid & 31;
    if (lane == 0) { sh0[wid] = s; sh1[wid] = ss; }
    __syncthreads();
    float tot = 0.f, tot2 = 0.f;
    #pragma unroll
    for (int i = 0; i < 8; i++) { tot += sh0[i]; tot2 += sh1[i]; }
    float mean = tot * (1.0f / DD);
    float var  = tot2 * (1.0f / DD) - mean * mean;
    float rstd = rsqrtf(var + 1e-7f);

    __half* orow = out + (size_t)row * DD;
    orow[tid      ] = __float2half_rn(gamma[tid      ] * (a - mean) * rstd + beta[tid      ]);
    orow[tid + 256] = __float2half_rn(gamma[tid + 256] * (b - mean) * rstd + beta[tid + 256]);
    orow[tid + 512] = __float2half_rn(gamma[tid + 512] * (c - mean) * rstd + beta[tid + 512]);
}

// ---------------- fp16 tensor-core GEMM: 128 threads, warp tile 64x64 -----
// C[M,N] = A[M,K](f16) @ Wt[N,K](f16)^T + bias(f32)
// CTA 128x128, BK=32, 4 warps (2x2), warp tile 64x64, m16n8k16 + ldmatrix.
// EPI: 0 = bias -> half | 1 = bias + resid -> f32 | 2 = bias + GELU -> half
template<int EPI>
__device__ __forceinline__ void hgemm_body(
    const __half* __restrict__ A, const __half* __restrict__ Wt,
    const float* __restrict__ bias, const float* __restrict__ resid,
    void* __restrict__ Cv, int K, int N)
{
    __shared__ __half As[2][128][40];
    __shared__ __half Bs[2][128][40];

    const int tid  = threadIdx.x;
    const int wid  = tid >> 5;
    const int lane = tid & 31;
    const int lr   = lane >> 2;
    const int lc   = lane & 3;
    const int wm   = wid >> 1;        // 0..1
    const int wn   = wid & 1;         // 0..1

    const int rowBase = blockIdx.y * 128;
    const int colBase = blockIdx.x * 128;

    float acc[4][8][4];
    #pragma unroll
    for (int i = 0; i < 4; i++)
        #pragma unroll
        for (int j = 0; j < 8; j++)
            #pragma unroll
            for (int q = 0; q < 4; q++) acc[i][j][q] = 0.f;

    auto load_tiles = [&](int buf, int k0) {
        #pragma unroll
        for (int i = 0; i < 4; i++) {
            int c = tid + i * 128;          // 0..511
            int r = c >> 2, ko = (c & 3) * 8;
            cp_async16(&As[buf][r][ko], A  + (size_t)(rowBase + r) * K + k0 + ko);
            cp_async16(&Bs[buf][r][ko], Wt + (size_t)(colBase + r) * K + k0 + ko);
        }
    };

    // ldmatrix lane addressing
    const int g = lane >> 3;                   // 0..3
    const int grow = lane & 7;
    const int aRowOff = ((g & 1) * 8 + grow);
    const int aColOff = (g >> 1) * 8;
    const int bRowOff = ((g >> 1) * 8 + grow);
    const int bColOff = (g & 1) * 8;

    const int niter = K >> 5;
    load_tiles(0, 0);
    CP_COMMIT();

    for (int it = 0; it < niter; it++) {
        const int buf = it & 1;
        if (it + 1 < niter) {
            load_tiles(buf ^ 1, (it + 1) << 5);
            CP_COMMIT();
            CP_WAIT(1);
        } else {
            CP_WAIT(0);
        }
        __syncthreads();

        #pragma unroll
        for (int kc = 0; kc < 2; kc++) {
            const int kk = kc * 16;
            uint32_t bf[8][2];
            #pragma unroll
            for (int jp = 0; jp < 4; jp++) {
                const int n = wn * 64 + jp * 16 + bRowOff;
                uint32_t addr = (uint32_t)__cvta_generic_to_shared(&Bs[buf][n][kk + bColOff]);
                ldsm_x4(bf[2*jp][0], bf[2*jp][1], bf[2*jp+1][0], bf[2*jp+1][1], addr);
            }
            #pragma unroll
            for (int i = 0; i < 4; i++) {
                const int m = wm * 64 + i * 16;
                uint32_t a[4];
                uint32_t addr = (uint32_t)__cvta_generic_to_shared(&As[buf][m + aRowOff][kk + aColOff]);
                ldsm_x4(a[0], a[1], a[2], a[3], addr);
                #pragma unroll
                for (int j = 0; j < 8; j++) mma_f16(acc[i][j], a, bf[j][0], bf[j][1]);
            }
        }
        __syncthreads();
    }

    // epilogue
    const int row0 = rowBase + wm * 64;
    const int col0 = colBase + wn * 64;
    __half* Ch = (__half*)Cv;
    float*  Cf = (float*)Cv;
    #pragma unroll
    for (int j = 0; j < 8; j++) {
        const int col = col0 + j * 8 + lc * 2;
        const float b0v = bias[col], b1v = bias[col + 1];
        #pragma unroll
        for (int i = 0; i < 4; i++) {
            const int r0 = row0 + i * 16 + lr;
            float v0 = acc[i][j][0] + b0v;
            float v1 = acc[i][j][1] + b1v;
            float v2 = acc[i][j][2] + b0v;
            float v3 = acc[i][j][3] + b1v;
            if (EPI == 1) {
                v0 += resid[(size_t)r0 * N + col];
                v1 += resid[(size_t)r0 * N + col + 1];
                v2 += resid[(size_t)(r0 + 8) * N + col];
                v3 += resid[(size_t)(r0 + 8) * N + col + 1];
                *(float2*)&Cf[(size_t)r0 * N + col]       = make_float2(v0, v1);
                *(float2*)&Cf[(size_t)(r0 + 8) * N + col] = make_float2(v2, v3);
            } else {
                if (EPI == 2) {
                    v0 = gelu_exact(v0); v1 = gelu_exact(v1);
                    v2 = gelu_exact(v2); v3 = gelu_exact(v3);
                }
                *(__half2*)&Ch[(size_t)r0 * N + col]       = __floats2half2_rn(v0, v1);
                *(__half2*)&Ch[(size_t)(r0 + 8) * N + col] = __floats2half2_rn(v2, v3);
            }
        }
    }
}

template<int EPI>
__global__ void __launch_bounds__(128, 2)
hgemm(const __half* __restrict__ A, const __half* __restrict__ Wt,
      const float* __restrict__ bias, const float* __restrict__ resid,
      void* __restrict__ C, int K, int N)
{
    hgemm_body<EPI>(A, Wt, bias, resid, C, K, N);
}

__global__ void __launch_bounds__(128, 2)
hgemm_qkv(const __half* __restrict__ A,
          const __half* __restrict__ wq, const __half* __restrict__ wk, const __half* __restrict__ wv,
          const float* __restrict__ bq, const float* __restrict__ bk, const float* __restrict__ bv,
          __half* __restrict__ qo, __half* __restrict__ ko, __half* __restrict__ vo,
          int K, int N)
{
    const __half* W  = (blockIdx.z == 0) ? wq : (blockIdx.z == 1) ? wk : wv;
    const float*  bi = (blockIdx.z == 0) ? bq : (blockIdx.z == 1) ? bk : bv;
    __half*       C  = (blockIdx.z == 0) ? qo : (blockIdx.z == 1) ? ko : vo;
    hgemm_body<0>(A, W, bi, nullptr, C, K, N);
}

// ---------------- fp16 mma.sync causal flash attention (R6, unchanged) ----------------
__global__ void __launch_bounds__(256)
attn_tc_kernel(const __half* __restrict__ q, const __half* __restrict__ k,
               const __half* __restrict__ v, __half* __restrict__ o)
{
    __shared__ __half sm[2][2][64][72];

    const int bh   = blockIdx.x;
    const int b    = bh / HH;
    const int h    = bh % HH;
    const int T    = (gridDim.y - 1) - blockIdx.y;
    const int q0   = T * 128;
    const int tid  = threadIdx.x;
    const int wid  = tid >> 5;
    const int lane = tid & 31;
    const int lr   = lane >> 2;
    const int lc   = lane & 3;
    const size_t headOff = (size_t)h * DKK;
    const size_t bBase   = (size_t)b * SS;

    {
        __half* Qst = &sm[0][0][0][0];
        #pragma unroll
        for (int i = 0; i < 4; i++) {
            int c = tid + i * 256;
            int r = c >> 3, ko = (c & 7) * 8;
            *(uint4*)&Qst[r * 72 + ko] = *(const uint4*)(q + (bBase + q0 + r) * DD + headOff + ko);
        }
    }
    __syncthreads();

    const __half2 qscale = __half2half2(__float2half(0.125f));
    uint32_t qf[4][4];
    const int qrow = wid * 16;
    {
        const __half* Qst = &sm[0][0][0][0];
        #pragma unroll
        for (int kc = 0; kc < 4; kc++) {
            const int kk = kc * 16;
            __half2 t0 = *(__half2*)&Qst[(qrow + lr    ) * 72 + kk + lc * 2];
            __half2 t1 = *(__half2*)&Qst[(qrow + 8 + lr) * 72 + kk + lc * 2];
            __half2 t2 = *(__half2*)&Qst[(qrow + lr    ) * 72 + kk + 8 + lc * 2];
            __half2 t3 = *(__half2*)&Qst[(qrow + 8 + lr) * 72 + kk + 8 + lc * 2];
            t0 = __hmul2(t0, qscale); t1 = __hmul2(t1, qscale);
            t2 = __hmul2(t2, qscale); t3 = __hmul2(t3, qscale);
            qf[kc][0] = *(uint32_t*)&t0; qf[kc][1] = *(uint32_t*)&t1;
            qf[kc][2] = *(uint32_t*)&t2; qf[kc][3] = *(uint32_t*)&t3;
        }
    }
    __syncthreads();

    auto loadKV = [&](int buf, int j0) {
        #pragma unroll
        for (int i = 0; i < 2; i++) {
            int c = tid + i * 256;
            int r = c >> 3, ko = (c & 7) * 8;
            cp_async16(&sm[buf][0][r][ko], k + (bBase + j0 + r) * DD + headOff + ko);
            cp_async16(&sm[buf][1][r][ko], v + (bBase + j0 + r) * DD + headOff + ko);
        }
    };

    const int gq = lane >> 3, rr = lane & 7;
    const uint32_t vlane = ((uint32_t)(((gq & 1) * 8 + rr) * 72 + (gq >> 1) * 8)) * 2;
    uint32_t vbase[2];
    vbase[0] = (uint32_t)__cvta_generic_to_shared(&sm[0][1][0][0]) + vlane;
    vbase[1] = (uint32_t)__cvta_generic_to_shared(&sm[1][1][0][0]) + vlane;

    float oacc[8][4];
    #pragma unroll
    for (int nv = 0; nv < 8; nv++)
        #pragma unroll
        for (int t = 0; t < 4; t++) oacc[nv][t] = 0.f;
    float m0 = -1e30f, m1 = -1e30f, l0 = 0.f, l1 = 0.f;

    const int qglob0 = q0 + qrow;
    const int nkt = 2 * T + 2;

    loadKV(0, 0);
    CP_COMMIT();

    for (int kt = 0; kt < nkt; kt++) {
        const int buf = kt & 1;
        const int j0 = kt * 64;
        if (kt + 1 < nkt) {
            loadKV(buf ^ 1, (kt + 1) * 64);
            CP_COMMIT();
            CP_WAIT(1);
        } else {
            CP_WAIT(0);
        }
        __syncthreads();

        if (j0 <= qglob0 + 15) {
            float sacc[8][4];
            #pragma unroll
            for (int nt = 0; nt < 8; nt++) {
                sacc[nt][0] = sacc[nt][1] = sacc[nt][2] = sacc[nt][3] = 0.f;
                #pragma unroll
                for (int kc = 0; kc < 4; kc++) {
                    const int kk = kc * 16;
                    uint32_t b0 = *(const uint32_t*)&sm[buf][0][nt * 8 + lr][kk + lc * 2];
                    uint32_t b1 = *(const uint32_t*)&sm[buf][0][nt * 8 + lr][kk + 8 + lc * 2];
                    mma_f16(sacc[nt], qf[kc], b0, b1);
                }
            }

            if (j0 + 63 > qglob0) {
                const int qi0 = qglob0 + lr, qi1 = qi0 + 8;
                #pragma unroll
                for (int nt = 0; nt < 8; nt++) {
                    const int kj = j0 + nt * 8 + lc * 2;
                    if (kj     > qi0) sacc[nt][0] = -1e30f;
                    if (kj + 1 > qi0) sacc[nt][1] = -1e30f;
                    if (kj     > qi1) sacc[nt][2] = -1e30f;
                    if (kj + 1 > qi1) sacc[nt][3] = -1e30f;
                }
            }

            float mx0 = -1e30f, mx1 = -1e30f;
            #pragma unroll
            for (int nt = 0; nt < 8; nt++) {
                mx0 = fmaxf(mx0, fmaxf(sacc[nt][0], sacc[nt][1]));
                mx1 = fmaxf(mx1, fmaxf(sacc[nt][2], sacc[nt][3]));
            }
            mx0 = fmaxf(mx0, __shfl_xor_sync(0xffffffffu, mx0, 1));
            mx0 = fmaxf(mx0, __shfl_xor_sync(0xffffffffu, mx0, 2));
            mx1 = fmaxf(mx1, __shfl_xor_sync(0xffffffffu, mx1, 1));
            mx1 = fmaxf(mx1, __shfl_xor_sync(0xffffffffu, mx1, 2));

            const float mn0 = fmaxf(m0, mx0);
            const float mn1 = fmaxf(m1, mx1);
            const float sc0 = __expf(m0 - mn0);
            const float sc1 = __expf(m1 - mn1);
            m0 = mn0; m1 = mn1;

            float la0 = 0.f, la1 = 0.f;
            #pragma unroll
            for (int nt = 0; nt < 8; nt++) {
                sacc[nt][0] = __expf(sacc[nt][0] - mn0);
                sacc[nt][1] = __expf(sacc[nt][1] - mn0);
                sacc[nt][2] = __expf(sacc[nt][2] - mn1);
                sacc[nt][3] = __expf(sacc[nt][3] - mn1);
                la0 += sacc[nt][0] + sacc[nt][1];
                la1 += sacc[nt][2] + sacc[nt][3];
            }
            la0 += __shfl_xor_sync(0xffffffffu, la0, 1);
            la0 += __shfl_xor_sync(0xffffffffu, la0, 2);
            la1 += __shfl_xor_sync(0xffffffffu, la1, 1);
            la1 += __shfl_xor_sync(0xffffffffu, la1, 2);
            l0 = l0 * sc0 + la0;
            l1 = l1 * sc1 + la1;

            #pragma unroll
            for (int nv = 0; nv < 8; nv++) {
                oacc[nv][0] *= sc0; oacc[nv][1] *= sc0;
                oacc[nv][2] *= sc1; oacc[nv][3] *= sc1;
            }

            uint32_t pf[4][4];
            #pragma unroll
            for (int pk = 0; pk < 4; pk++) {
                __half2 h0 = __floats2half2_rn(sacc[2*pk    ][0], sacc[2*pk    ][1]);
                __half2 h1 = __floats2half2_rn(sacc[2*pk    ][2], sacc[2*pk    ][3]);
                __half2 h2 = __floats2half2_rn(sacc[2*pk + 1][0], sacc[2*pk + 1][1]);
                __half2 h3 = __floats2half2_rn(sacc[2*pk + 1][2], sacc[2*pk + 1][3]);
                pf[pk][0] = *(uint32_t*)&h0;
                pf[pk][1] = *(uint32_t*)&h1;
                pf[pk][2] = *(uint32_t*)&h2;
                pf[pk][3] = *(uint32_t*)&h3;
            }

            #pragma unroll
            for (int nh = 0; nh < 4; nh++) {
                #pragma unroll
                for (int pk = 0; pk < 4; pk++) {
                    uint32_t b0, b1, b2, b3;
                    ldsm_x4_t(b0, b1, b2, b3, vbase[buf] + pk * 2304 + nh * 32);
                    mma_f16(oacc[2*nh    ], pf[pk], b0, b1);
                    mma_f16(oacc[2*nh + 1], pf[pk], b2, b3);
                }
            }
        }
        __syncthreads();
    }

    const float inv0 = 1.f / l0;
    const float inv1 = 1.f / l1;
    const size_t r0 = bBase + q0 + qrow + lr;
    #pragma unroll
    for (int nv = 0; nv < 8; nv++) {
        const int col = nv * 8 + lc * 2;
        *(__half2*)&o[r0 * DD + headOff + col] =
            __floats2half2_rn(oacc[nv][0] * inv0, oacc[nv][1] * inv0);
        *(__half2*)&o[(r0 + 8) * DD + headOff + col] =
            __floats2half2_rn(oacc[nv][2] * inv1, oacc[nv][3] * inv1);
    }
}

// ---------------- host launcher ----------------
extern "C" void kernel_launch(void* const* d_in, const int* in_sizes, int n_in,
                              void* d_out, int out_size)
{
    const float* x    = (const float*)d_in[0];
    const float* ln1g = (const float*)d_in[1];
    const float* ln1b = (const float*)d_in[2];
    const float* wq   = (const float*)d_in[3];
    const float* bq   = (const float*)d_in[4];
    const float* wk   = (const float*)d_in[5];
    const float* bk   = (const float*)d_in[6];
    const float* wv   = (const float*)d_in[7];
    const float* bv   = (const float*)d_in[8];
    const float* wo   = (const float*)d_in[9];
    const float* bo   = (const float*)d_in[10];
    const float* ln2g = (const float*)d_in[11];
    const float* ln2b = (const float*)d_in[12];
    const float* w1   = (const float*)d_in[13];
    const float* b1   = (const float*)d_in[14];
    const float* w2   = (const float*)d_in[15];
    const float* b2   = (const float*)d_in[16];
    float* out = (float*)d_out;

    __half *ln1, *qb, *kb, *vb, *attn, *ln2, *ffn1;
    __half *twq, *twk, *twv, *two, *tw1, *tw2;
    float *x1;
    cudaGetSymbolAddress((void**)&ln1,  h_ln1);
    cudaGetSymbolAddress((void**)&qb,   h_q);
    cudaGetSymbolAddress((void**)&kb,   h_k);
    cudaGetSymbolAddress((void**)&vb,   h_v);
    cudaGetSymbolAddress((void**)&attn, h_attn);
    cudaGetSymbolAddress((void**)&x1,   g_x1);
    cudaGetSymbolAddress((void**)&ln2,  h_ln2);
    cudaGetSymbolAddress((void**)&ffn1, h_ffn1);
    cudaGetSymbolAddress((void**)&twq,  h_wq);
    cudaGetSymbolAddress((void**)&twk,  h_wk);
    cudaGetSymbolAddress((void**)&twv,  h_wv);
    cudaGetSymbolAddress((void**)&two,  h_wo);
    cudaGetSymbolAddress((void**)&tw1,  h_w1);
    cudaGetSymbolAddress((void**)&tw2,  h_w2);

    // 0) all weight converts in one launch
    wconv_all<<<6912, dim3(32, 8)>>>(wq, wk, wv, wo, w1, w2,
                                     twq, twk, twv, two, tw1, tw2);

    // 1) LN1 -> half
    ln_kernel<<<MROWS, 256>>>(x, ln1g, ln1b, ln1);

    // 2) QKV projections
    hgemm_qkv<<<dim3(DD / 128, MROWS / 128, 3), 128>>>(
        ln1, twq, twk, twv, bq, bk, bv, qb, kb, vb, DD, DD);

    // 3) causal attention (128-query tiles, 8 warps)
    attn_tc_kernel<<<dim3(BB * HH, SS / 128), 256>>>(qb, kb, vb, attn);

    // 4) O projection + residual -> f32 x1
    hgemm<1><<<dim3(DD / 128, MROWS / 128), 128>>>(attn, two, bo, x, x1, DD, DD);

    // 5) LN2 -> half
    ln_kernel<<<MROWS, 256>>>(x1, ln2g, ln2b, ln2);

    // 6) FFN up + GELU -> half
    hgemm<2><<<dim3(DFF / 128, MROWS / 128), 128>>>(ln2, tw1, b1, nullptr, ffn1, DD, DFF);

    // 7) FFN down + residual -> f32 out
    hgemm<1><<<dim3(DD / 128, MROWS / 128), 128>>>(ffn1, tw2, b2, x1, out, DFF, DD);
}

// round 9
// speedup vs baseline: 7.2565x; 1.0124x over previous
#include <cuda_runtime.h>
#include <cuda_fp16.h>
#include <math.h>
#include <stdint.h>

#define BB 2
#define SS 2048
#define DD 768
#define HH 12
#define DKK 64
#define DFF 3072
#define MROWS (BB*SS)   // 4096

// ---------------- scratch (device globals: allocation-free) ----------------
__device__ __half h_ln1 [MROWS*DD];
__device__ __half h_q   [MROWS*DD];
__device__ __half h_k   [MROWS*DD];
__device__ __half h_v   [MROWS*DD];
__device__ __half h_attn[MROWS*DD];
__device__ float  g_x1  [MROWS*DD];
__device__ __half h_ln2 [MROWS*DD];
__device__ __half h_ffn1[MROWS*DFF];
// transposed half weights: Wt[N][K]
__device__ __half h_wq[DD*DD];
__device__ __half h_wk[DD*DD];
__device__ __half h_wv[DD*DD];
__device__ __half h_wo[DD*DD];
__device__ __half h_w1[DD*DFF];
__device__ __half h_w2[DFF*DD];

// ---------------- helpers ----------------
__device__ __forceinline__ float gelu_exact(float v) {
    return 0.5f * v * (1.0f + erff(v * 0.70710678118654752f));
}
__device__ __forceinline__ void cp_async16(void* smem, const void* gmem) {
    uint32_t s = (uint32_t)__cvta_generic_to_shared(smem);
    asm volatile("cp.async.cg.shared.global [%0], [%1], 16;\n" :: "r"(s), "l"(gmem));
}
#define CP_COMMIT() asm volatile("cp.async.commit_group;\n" ::)
#define CP_WAIT(n)  asm volatile("cp.async.wait_group %0;\n" :: "n"(n))

__device__ __forceinline__ void mma_f16(float* c, const uint32_t* a, uint32_t b0, uint32_t b1) {
    asm volatile(
      "mma.sync.aligned.m16n8k16.row.col.f32.f16.f16.f32 "
      "{%0,%1,%2,%3}, {%4,%5,%6,%7}, {%8,%9}, {%0,%1,%2,%3};\n"
      : "+f"(c[0]), "+f"(c[1]), "+f"(c[2]), "+f"(c[3])
      : "r"(a[0]), "r"(a[1]), "r"(a[2]), "r"(a[3]), "r"(b0), "r"(b1));
}
__device__ __forceinline__ void ldsm_x4(uint32_t& r0, uint32_t& r1, uint32_t& r2, uint32_t& r3,
                                        uint32_t addr) {
    asm volatile("ldmatrix.sync.aligned.m8n8.x4.shared.b16 {%0,%1,%2,%3}, [%4];\n"
      : "=r"(r0), "=r"(r1), "=r"(r2), "=r"(r3) : "r"(addr));
}
__device__ __forceinline__ void ldsm_x4_t(uint32_t& r0, uint32_t& r1, uint32_t& r2, uint32_t& r3,
                                          uint32_t addr) {
    asm volatile("ldmatrix.sync.aligned.m8n8.x4.trans.shared.b16 {%0,%1,%2,%3}, [%4];\n"
      : "=r"(r0), "=r"(r1), "=r"(r2), "=r"(r3) : "r"(addr));
}

// ---------------- fused weight transpose + f32->f16 convert ----------------
__global__ void wconv_all(const float* __restrict__ wq, const float* __restrict__ wk,
                          const float* __restrict__ wv, const float* __restrict__ wo,
                          const float* __restrict__ w1, const float* __restrict__ w2,
                          __half* __restrict__ twq, __half* __restrict__ twk,
                          __half* __restrict__ twv, __half* __restrict__ two,
                          __half* __restrict__ tw1, __half* __restrict__ tw2)
{
    const int idx = blockIdx.x;
    const float* W; __half* Wt; int K, N, tk, tn;
    if (idx < 2304) {
        const int which = idx / 576, r = idx % 576;
        W  = (which == 0) ? wq  : (which == 1) ? wk  : (which == 2) ? wv  : wo;
        Wt = (which == 0) ? twq : (which == 1) ? twk : (which == 2) ? twv : two;
        K = DD; N = DD; tk = r % 24; tn = r / 24;
    } else if (idx < 4608) {
        const int r = idx - 2304;
        W = w1; Wt = tw1; K = DD; N = DFF; tk = r % 24; tn = r / 24;
    } else {
        const int r = idx - 4608;
        W = w2; Wt = tw2; K = DFF; N = DD; tk = r % 96; tn = r / 96;
    }
    __shared__ float t[32][33];
    const int k0 = tk * 32, n0 = tn * 32;
    const int tx = threadIdx.x, ty = threadIdx.y;
    #pragma unroll
    for (int i = 0; i < 32; i += 8)
        t[ty + i][tx] = W[(size_t)(k0 + ty + i) * N + n0 + tx];
    __syncthreads();
    #pragma unroll
    for (int i = 0; i < 32; i += 8)
        Wt[(size_t)(n0 + ty + i) * K + k0 + tx] = __float2half_rn(t[tx][ty + i]);
}

// ---------------- LayerNorm: f32 in, f16 out ----------------
__global__ void ln_kernel(const float* __restrict__ x,
                          const float* __restrict__ gamma,
                          const float* __restrict__ beta,
                          __half* __restrict__ out)
{
    int row = blockIdx.x;
    const float* xr = x + (size_t)row * DD;
    int tid = threadIdx.x;

    float a = xr[tid], b = xr[tid + 256], c = xr[tid + 512];
    float s  = a + b + c;
    float ss = a*a + b*b + c*c;
    #pragma unroll
    for (int off = 16; off > 0; off >>= 1) {
        s  += __shfl_xor_sync(0xffffffffu, s,  off);
        ss += __shfl_xor_sync(0xffffffffu, ss, off);
    }
    __shared__ float sh0[8], sh1[8];
    int wid = tid >> 5, lane = tid & 31;
    if (lane == 0) { sh0[wid] = s; sh1[wid] = ss; }
    __syncthreads();
    float tot = 0.f, tot2 = 0.f;
    #pragma unroll
    for (int i = 0; i < 8; i++) { tot += sh0[i]; tot2 += sh1[i]; }
    float mean = tot * (1.0f / DD);
    float var  = tot2 * (1.0f / DD) - mean * mean;
    float rstd = rsqrtf(var + 1e-7f);

    __half* orow = out + (size_t)row * DD;
    orow[tid      ] = __float2half_rn(gamma[tid      ] * (a - mean) * rstd + beta[tid      ]);
    orow[tid + 256] = __float2half_rn(gamma[tid + 256] * (b - mean) * rstd + beta[tid + 256]);
    orow[tid + 512] = __float2half_rn(gamma[tid + 512] * (c - mean) * rstd + beta[tid + 512]);
}

// ---------------- fp16 tensor-core GEMM: 4-stage ring, 1 sync/iter --------
// C[M,N] = A[M,K](f16) @ Wt[N,K](f16)^T + bias(f32)
// CTA 128x128, BK=32, 4 warps (2x2), warp tile 64x64, m16n8k16 + ldmatrix.
// 4-stage cp.async ring: prefetch distance 2, single __syncthreads per iter.
// EPI: 0 = bias -> half | 1 = bias + resid -> f32 | 2 = bias + GELU -> half
#define STAGE_BYTES 20480            // As 128x40x2 + Bs 128x40x2
#define GSMEM (4*STAGE_BYTES)        // 81,920 B

template<int EPI>
__device__ __forceinline__ void hgemm_body(
    const __half* __restrict__ A, const __half* __restrict__ Wt,
    const float* __restrict__ bias, const float* __restrict__ resid,
    void* __restrict__ Cv, int K, int N)
{
    extern __shared__ __align__(16) char dsm[];

    const int tid  = threadIdx.x;
    const int wid  = tid >> 5;
    const int lane = tid & 31;
    const int lr   = lane >> 2;
    const int lc   = lane & 3;
    const int wm   = wid >> 1;        // 0..1
    const int wn   = wid & 1;         // 0..1

    const int rowBase = blockIdx.y * 128;
    const int colBase = blockIdx.x * 128;

    float acc[4][8][4];
    #pragma unroll
    for (int i = 0; i < 4; i++)
        #pragma unroll
        for (int j = 0; j < 8; j++)
            #pragma unroll
            for (int q = 0; q < 4; q++) acc[i][j][q] = 0.f;

    auto load_tiles = [&](int st, int k0) {
        __half (*As)[40] = (__half(*)[40])(dsm + st * STAGE_BYTES);
        __half (*Bs)[40] = (__half(*)[40])(dsm + st * STAGE_BYTES + 10240);
        #pragma unroll
        for (int i = 0; i < 4; i++) {
            int c = tid + i * 128;          // 0..511
            int r = c >> 2, ko = (c & 3) * 8;
            cp_async16(&As[r][ko], A  + (size_t)(rowBase + r) * K + k0 + ko);
            cp_async16(&Bs[r][ko], Wt + (size_t)(colBase + r) * K + k0 + ko);
        }
    };

    // ldmatrix lane addressing
    const int g = lane >> 3;                   // 0..3
    const int grow = lane & 7;
    const int aRowOff = ((g & 1) * 8 + grow);
    const int aColOff = (g >> 1) * 8;
    const int bRowOff = ((g >> 1) * 8 + grow);
    const int bColOff = (g & 1) * 8;

    const int niter = K >> 5;                  // >= 24 for all our shapes
    load_tiles(0, 0);  CP_COMMIT();
    load_tiles(1, 32); CP_COMMIT();

    for (int it = 0; it < niter; it++) {
        const int st  = it & 3;
        const int pre = it + 2;
        if (pre < niter) {
            load_tiles(pre & 3, pre << 5);
            CP_COMMIT();
            CP_WAIT(2);
        } else if (it + 1 < niter) {
            CP_WAIT(1);
        } else {
            CP_WAIT(0);
        }
        __syncthreads();

        __half (*As)[40] = (__half(*)[40])(dsm + st * STAGE_BYTES);
        __half (*Bs)[40] = (__half(*)[40])(dsm + st * STAGE_BYTES + 10240);
        #pragma unroll
        for (int kc = 0; kc < 2; kc++) {
            const int kk = kc * 16;
            uint32_t bf[8][2];
            #pragma unroll
            for (int jp = 0; jp < 4; jp++) {
                const int n = wn * 64 + jp * 16 + bRowOff;
                uint32_t addr = (uint32_t)__cvta_generic_to_shared(&Bs[n][kk + bColOff]);
                ldsm_x4(bf[2*jp][0], bf[2*jp][1], bf[2*jp+1][0], bf[2*jp+1][1], addr);
            }
            #pragma unroll
            for (int i = 0; i < 4; i++) {
                const int m = wm * 64 + i * 16;
                uint32_t a[4];
                uint32_t addr = (uint32_t)__cvta_generic_to_shared(&As[m + aRowOff][kk + aColOff]);
                ldsm_x4(a[0], a[1], a[2], a[3], addr);
                #pragma unroll
                for (int j = 0; j < 8; j++) mma_f16(acc[i][j], a, bf[j][0], bf[j][1]);
            }
        }
    }

    // epilogue (registers only; no smem dependence)
    const int row0 = rowBase + wm * 64;
    const int col0 = colBase + wn * 64;
    __half* Ch = (__half*)Cv;
    float*  Cf = (float*)Cv;
    #pragma unroll
    for (int j = 0; j < 8; j++) {
        const int col = col0 + j * 8 + lc * 2;
        const float b0v = bias[col], b1v = bias[col + 1];
        #pragma unroll
        for (int i = 0; i < 4; i++) {
            const int r0 = row0 + i * 16 + lr;
            float v0 = acc[i][j][0] + b0v;
            float v1 = acc[i][j][1] + b1v;
            float v2 = acc[i][j][2] + b0v;
            float v3 = acc[i][j][3] + b1v;
            if (EPI == 1) {
                v0 += resid[(size_t)r0 * N + col];
                v1 += resid[(size_t)r0 * N + col + 1];
                v2 += resid[(size_t)(r0 + 8) * N + col];
                v3 += resid[(size_t)(r0 + 8) * N + col + 1];
                *(float2*)&Cf[(size_t)r0 * N + col]       = make_float2(v0, v1);
                *(float2*)&Cf[(size_t)(r0 + 8) * N + col] = make_float2(v2, v3);
            } else {
                if (EPI == 2) {
                    v0 = gelu_exact(v0); v1 = gelu_exact(v1);
                    v2 = gelu_exact(v2); v3 = gelu_exact(v3);
                }
                *(__half2*)&Ch[(size_t)r0 * N + col]       = __floats2half2_rn(v0, v1);
                *(__half2*)&Ch[(size_t)(r0 + 8) * N + col] = __floats2half2_rn(v2, v3);
            }
        }
    }
}

template<int EPI>
__global__ void __launch_bounds__(128, 2)
hgemm(const __half* __restrict__ A, const __half* __restrict__ Wt,
      const float* __restrict__ bias, const float* __restrict__ resid,
      void* __restrict__ C, int K, int N)
{
    hgemm_body<EPI>(A, Wt, bias, resid, C, K, N);
}

__global__ void __launch_bounds__(128, 2)
hgemm_qkv(const __half* __restrict__ A,
          const __half* __restrict__ wq, const __half* __restrict__ wk, const __half* __restrict__ wv,
          const float* __restrict__ bq, const float* __restrict__ bk, const float* __restrict__ bv,
          __half* __restrict__ qo, __half* __restrict__ ko, __half* __restrict__ vo,
          int K, int N)
{
    const __half* W  = (blockIdx.z == 0) ? wq : (blockIdx.z == 1) ? wk : wv;
    const float*  bi = (blockIdx.z == 0) ? bq : (blockIdx.z == 1) ? bk : bv;
    __half*       C  = (blockIdx.z == 0) ? qo : (blockIdx.z == 1) ? ko : vo;
    hgemm_body<0>(A, W, bi, nullptr, C, K, N);
}

// ---------------- fp16 mma.sync causal flash attention ----------------
// grid (B*H, S/128), 256 threads (8 warps); each warp owns 16 query rows.
// QK and PV both via ldmatrix.x4 (non-trans for K, trans for V).
__global__ void __launch_bounds__(256)
attn_tc_kernel(const __half* __restrict__ q, const __half* __restrict__ k,
               const __half* __restrict__ v, __half* __restrict__ o)
{
    __shared__ __half sm[2][2][64][72];

    const int bh   = blockIdx.x;
    const int b    = bh / HH;
    const int h    = bh % HH;
    const int T    = (gridDim.y - 1) - blockIdx.y;
    const int q0   = T * 128;
    const int tid  = threadIdx.x;
    const int wid  = tid >> 5;
    const int lane = tid & 31;
    const int lr   = lane >> 2;
    const int lc   = lane & 3;
    const size_t headOff = (size_t)h * DKK;
    const size_t bBase   = (size_t)b * SS;

    {
        __half* Qst = &sm[0][0][0][0];
        #pragma unroll
        for (int i = 0; i < 4; i++) {
            int c = tid + i * 256;
            int r = c >> 3, ko = (c & 7) * 8;
            *(uint4*)&Qst[r * 72 + ko] = *(const uint4*)(q + (bBase + q0 + r) * DD + headOff + ko);
        }
    }
    __syncthreads();

    const __half2 qscale = __half2half2(__float2half(0.125f));
    uint32_t qf[4][4];
    const int qrow = wid * 16;
    {
        const __half* Qst = &sm[0][0][0][0];
        #pragma unroll
        for (int kc = 0; kc < 4; kc++) {
            const int kk = kc * 16;
            __half2 t0 = *(__half2*)&Qst[(qrow + lr    ) * 72 + kk + lc * 2];
            __half2 t1 = *(__half2*)&Qst[(qrow + 8 + lr) * 72 + kk + lc * 2];
            __half2 t2 = *(__half2*)&Qst[(qrow + lr    ) * 72 + kk + 8 + lc * 2];
            __half2 t3 = *(__half2*)&Qst[(qrow + 8 + lr) * 72 + kk + 8 + lc * 2];
            t0 = __hmul2(t0, qscale); t1 = __hmul2(t1, qscale);
            t2 = __hmul2(t2, qscale); t3 = __hmul2(t3, qscale);
            qf[kc][0] = *(uint32_t*)&t0; qf[kc][1] = *(uint32_t*)&t1;
            qf[kc][2] = *(uint32_t*)&t2; qf[kc][3] = *(uint32_t*)&t3;
        }
    }
    __syncthreads();

    auto loadKV = [&](int buf, int j0) {
        #pragma unroll
        for (int i = 0; i < 2; i++) {
            int c = tid + i * 256;
            int r = c >> 3, ko = (c & 7) * 8;
            cp_async16(&sm[buf][0][r][ko], k + (bBase + j0 + r) * DD + headOff + ko);
            cp_async16(&sm[buf][1][r][ko], v + (bBase + j0 + r) * DD + headOff + ko);
        }
    };

    // ldmatrix lane base offsets (bytes)
    const int gq = lane >> 3, rr = lane & 7;
    // V (trans): row = (gq&1)*8+rr, col = (gq>>1)*8
    const uint32_t vlane = ((uint32_t)(((gq & 1) * 8 + rr) * 72 + (gq >> 1) * 8)) * 2;
    // K (non-trans B-frag): row = (gq>>1)*8+rr, col = (gq&1)*8
    const uint32_t klane = ((uint32_t)(((gq >> 1) * 8 + rr) * 72 + (gq & 1) * 8)) * 2;
    uint32_t vbase[2], kbase[2];
    vbase[0] = (uint32_t)__cvta_generic_to_shared(&sm[0][1][0][0]) + vlane;
    vbase[1] = (uint32_t)__cvta_generic_to_shared(&sm[1][1][0][0]) + vlane;
    kbase[0] = (uint32_t)__cvta_generic_to_shared(&sm[0][0][0][0]) + klane;
    kbase[1] = (uint32_t)__cvta_generic_to_shared(&sm[1][0][0][0]) + klane;

    float oacc[8][4];
    #pragma unroll
    for (int nv = 0; nv < 8; nv++)
        #pragma unroll
        for (int t = 0; t < 4; t++) oacc[nv][t] = 0.f;
    float m0 = -1e30f, m1 = -1e30f, l0 = 0.f, l1 = 0.f;

    const int qglob0 = q0 + qrow;
    const int nkt = 2 * T + 2;

    loadKV(0, 0);
    CP_COMMIT();

    for (int kt = 0; kt < nkt; kt++) {
        const int buf = kt & 1;
        const int j0 = kt * 64;
        if (kt + 1 < nkt) {
            loadKV(buf ^ 1, (kt + 1) * 64);
            CP_COMMIT();
            CP_WAIT(1);
        } else {
            CP_WAIT(0);
        }
        __syncthreads();

        if (j0 <= qglob0 + 15) {
            // ---- S = Q K^T : ldmatrix.x4 K B-frags, 16 ldsm + 32 mma ----
            float sacc[8][4];
            #pragma unroll
            for (int nt = 0; nt < 8; nt++)
                sacc[nt][0] = sacc[nt][1] = sacc[nt][2] = sacc[nt][3] = 0.f;
            #pragma unroll
            for (int kc = 0; kc < 4; kc++) {
                #pragma unroll
                for (int np = 0; np < 4; np++) {
                    uint32_t b0, b1, b2, b3;
                    ldsm_x4(b0, b1, b2, b3, kbase[buf] + np * 2304 + kc * 32);
                    mma_f16(sacc[2*np    ], qf[kc], b0, b1);
                    mma_f16(sacc[2*np + 1], qf[kc], b2, b3);
                }
            }

            if (j0 + 63 > qglob0) {
                const int qi0 = qglob0 + lr, qi1 = qi0 + 8;
                #pragma unroll
                for (int nt = 0; nt < 8; nt++) {
                    const int kj = j0 + nt * 8 + lc * 2;
                    if (kj     > qi0) sacc[nt][0] = -1e30f;
                    if (kj + 1 > qi0) sacc[nt][1] = -1e30f;
                    if (kj     > qi1) sacc[nt][2] = -1e30f;
                    if (kj + 1 > qi1) sacc[nt][3] = -1e30f;
                }
            }

            float mx0 = -1e30f, mx1 = -1e30f;
            #pragma unroll
            for (int nt = 0; nt < 8; nt++) {
                mx0 = fmaxf(mx0, fmaxf(sacc[nt][0], sacc[nt][1]));
                mx1 = fmaxf(mx1, fmaxf(sacc[nt][2], sacc[nt][3]));
            }
            mx0 = fmaxf(mx0, __shfl_xor_sync(0xffffffffu, mx0, 1));
            mx0 = fmaxf(mx0, __shfl_xor_sync(0xffffffffu, mx0, 2));
            mx1 = fmaxf(mx1, __shfl_xor_sync(0xffffffffu, mx1, 1));
            mx1 = fmaxf(mx1, __shfl_xor_sync(0xffffffffu, mx1, 2));

            const float mn0 = fmaxf(m0, mx0);
            const float mn1 = fmaxf(m1, mx1);
            const float sc0 = __expf(m0 - mn0);
            const float sc1 = __expf(m1 - mn1);
            m0 = mn0; m1 = mn1;

            float la0 = 0.f, la1 = 0.f;
            #pragma unroll
            for (int nt = 0; nt < 8; nt++) {
                sacc[nt][0] = __expf(sacc[nt][0] - mn0);
                sacc[nt][1] = __expf(sacc[nt][1] - mn0);
                sacc[nt][2] = __expf(sacc[nt][2] - mn1);
                sacc[nt][3] = __expf(sacc[nt][3] - mn1);
                la0 += sacc[nt][0] + sacc[nt][1];
                la1 += sacc[nt][2] + sacc[nt][3];
            }
            la0 += __shfl_xor_sync(0xffffffffu, la0, 1);
            la0 += __shfl_xor_sync(0xffffffffu, la0, 2);
            la1 += __shfl_xor_sync(0xffffffffu, la1, 1);
            la1 += __shfl_xor_sync(0xffffffffu, la1, 2);
            l0 = l0 * sc0 + la0;
            l1 = l1 * sc1 + la1;

            #pragma unroll
            for (int nv = 0; nv < 8; nv++) {
                oacc[nv][0] *= sc0; oacc[nv][1] *= sc0;
                oacc[nv][2] *= sc1; oacc[nv][3] *= sc1;
            }

            uint32_t pf[4][4];
            #pragma unroll
            for (int pk = 0; pk < 4; pk++) {
                __half2 h0 = __floats2half2_rn(sacc[2*pk    ][0], sacc[2*pk    ][1]);
                __half2 h1 = __floats2half2_rn(sacc[2*pk    ][2], sacc[2*pk    ][3]);
                __half2 h2 = __floats2half2_rn(sacc[2*pk + 1][0], sacc[2*pk + 1][1]);
                __half2 h3 = __floats2half2_rn(sacc[2*pk + 1][2], sacc[2*pk + 1][3]);
                pf[pk][0] = *(uint32_t*)&h0;
                pf[pk][1] = *(uint32_t*)&h1;
                pf[pk][2] = *(uint32_t*)&h2;
                pf[pk][3] = *(uint32_t*)&h3;
            }

            #pragma unroll
            for (int nh = 0; nh < 4; nh++) {
                #pragma unroll
                for (int pk = 0; pk < 4; pk++) {
                    uint32_t b0, b1, b2, b3;
                    ldsm_x4_t(b0, b1, b2, b3, vbase[buf] + pk * 2304 + nh * 32);
                    mma_f16(oacc[2*nh    ], pf[pk], b0, b1);
                    mma_f16(oacc[2*nh + 1], pf[pk], b2, b3);
                }
            }
        }
        __syncthreads();
    }

    const float inv0 = 1.f / l0;
    const float inv1 = 1.f / l1;
    const size_t r0 = bBase + q0 + qrow + lr;
    #pragma unroll
    for (int nv = 0; nv < 8; nv++) {
        const int col = nv * 8 + lc * 2;
        *(__half2*)&o[r0 * DD + headOff + col] =
            __floats2half2_rn(oacc[nv][0] * inv0, oacc[nv][1] * inv0);
        *(__half2*)&o[(r0 + 8) * DD + headOff + col] =
            __floats2half2_rn(oacc[nv][2] * inv1, oacc[nv][3] * inv1);
    }
}

// ---------------- host launcher ----------------
extern "C" void kernel_launch(void* const* d_in, const int* in_sizes, int n_in,
                              void* d_out, int out_size)
{
    const float* x    = (const float*)d_in[0];
    const float* ln1g = (const float*)d_in[1];
    const float* ln1b = (const float*)d_in[2];
    const float* wq   = (const float*)d_in[3];
    const float* bq   = (const float*)d_in[4];
    const float* wk   = (const float*)d_in[5];
    const float* bk   = (const float*)d_in[6];
    const float* wv   = (const float*)d_in[7];
    const float* bv   = (const float*)d_in[8];
    const float* wo   = (const float*)d_in[9];
    const float* bo   = (const float*)d_in[10];
    const float* ln2g = (const float*)d_in[11];
    const float* ln2b = (const float*)d_in[12];
    const float* w1   = (const float*)d_in[13];
    const float* b1   = (const float*)d_in[14];
    const float* w2   = (const float*)d_in[15];
    const float* b2   = (const float*)d_in[16];
    float* out = (float*)d_out;

    __half *ln1, *qb, *kb, *vb, *attn, *ln2, *ffn1;
    __half *twq, *twk, *twv, *two, *tw1, *tw2;
    float *x1;
    cudaGetSymbolAddress((void**)&ln1,  h_ln1);
    cudaGetSymbolAddress((void**)&qb,   h_q);
    cudaGetSymbolAddress((void**)&kb,   h_k);
    cudaGetSymbolAddress((void**)&vb,   h_v);
    cudaGetSymbolAddress((void**)&attn, h_attn);
    cudaGetSymbolAddress((void**)&x1,   g_x1);
    cudaGetSymbolAddress((void**)&ln2,  h_ln2);
    cudaGetSymbolAddress((void**)&ffn1, h_ffn1);
    cudaGetSymbolAddress((void**)&twq,  h_wq);
    cudaGetSymbolAddress((void**)&twk,  h_wk);
    cudaGetSymbolAddress((void**)&twv,  h_wv);
    cudaGetSymbolAddress((void**)&two,  h_wo);
    cudaGetSymbolAddress((void**)&tw1,  h_w1);
    cudaGetSymbolAddress((void**)&tw2,  h_w2);

    cudaFuncSetAttribute(hgemm<0>,  cudaFuncAttributeMaxDynamicSharedMemorySize, GSMEM);
    cudaFuncSetAttribute(hgemm<1>,  cudaFuncAttributeMaxDynamicSharedMemorySize, GSMEM);
    cudaFuncSetAttribute(hgemm<2>,  cudaFuncAttributeMaxDynamicSharedMemorySize, GSMEM);
    cudaFuncSetAttribute(hgemm_qkv, cudaFuncAttributeMaxDynamicSharedMemorySize, GSMEM);

    // 0) all weight converts in one launch
    wconv_all<<<6912, dim3(32, 8)>>>(wq, wk, wv, wo, w1, w2,
                                     twq, twk, twv, two, tw1, tw2);

    // 1) LN1 -> half
    ln_kernel<<<MROWS, 256>>>(x, ln1g, ln1b, ln1);

    // 2) QKV projections
    hgemm_qkv<<<dim3(DD / 128, MROWS / 128, 3), 128, GSMEM>>>(
        ln1, twq, twk, twv, bq, bk, bv, qb, kb, vb, DD, DD);

    // 3) causal attention (128-query tiles, 8 warps)
    attn_tc_kernel<<<dim3(BB * HH, SS / 128), 256>>>(qb, kb, vb, attn);

    // 4) O projection + residual -> f32 x1
    hgemm<1><<<dim3(DD / 128, MROWS / 128), 128, GSMEM>>>(attn, two, bo, x, x1, DD, DD);

    // 5) LN2 -> half
    ln_kernel<<<MROWS, 256>>>(x1, ln2g, ln2b, ln2);

    // 6) FFN up + GELU -> half
    hgemm<2><<<dim3(DFF / 128, MROWS / 128), 128, GSMEM>>>(ln2, tw1, b1, nullptr, ffn1, DD, DFF);

    // 7) FFN down + residual -> f32 out
    hgemm<1><<<dim3(DD / 128, MROWS / 128), 128, GSMEM>>>(ffn1, tw2, b2, x1, out, DFF, DD);
}

// round 10
// speedup vs baseline: 7.3948x; 1.0191x over previous
#include <cuda_runtime.h>
#include <cuda_fp16.h>
#include <math.h>
#include <stdint.h>

#define BB 2
#define SS 2048
#define DD 768
#define HH 12
#define DKK 64
#define DFF 3072
#define MROWS (BB*SS)   // 4096

// ---------------- scratch (device globals: allocation-free) ----------------
__device__ __half h_ln1 [MROWS*DD];
__device__ __half h_q   [MROWS*DD];
__device__ __half h_k   [MROWS*DD];
__device__ __half h_v   [MROWS*DD];
__device__ __half h_attn[MROWS*DD];
__device__ float  g_x1  [MROWS*DD];
__device__ __half h_ln2 [MROWS*DD];
__device__ __half h_ffn1[MROWS*DFF];
// transposed half weights: Wt[N][K]
__device__ __half h_wq[DD*DD];
__device__ __half h_wk[DD*DD];
__device__ __half h_wv[DD*DD];
__device__ __half h_wo[DD*DD];
__device__ __half h_w1[DD*DFF];
__device__ __half h_w2[DFF*DD];

// ---------------- helpers ----------------
__device__ __forceinline__ float gelu_exact(float v) {
    return 0.5f * v * (1.0f + erff(v * 0.70710678118654752f));
}
__device__ __forceinline__ void cp_async16(void* smem, const void* gmem) {
    uint32_t s = (uint32_t)__cvta_generic_to_shared(smem);
    asm volatile("cp.async.cg.shared.global [%0], [%1], 16;\n" :: "r"(s), "l"(gmem));
}
#define CP_COMMIT() asm volatile("cp.async.commit_group;\n" ::)
#define CP_WAIT(n)  asm volatile("cp.async.wait_group %0;\n" :: "n"(n))

__device__ __forceinline__ void mma_f16(float* c, const uint32_t* a, uint32_t b0, uint32_t b1) {
    asm volatile(
      "mma.sync.aligned.m16n8k16.row.col.f32.f16.f16.f32 "
      "{%0,%1,%2,%3}, {%4,%5,%6,%7}, {%8,%9}, {%0,%1,%2,%3};\n"
      : "+f"(c[0]), "+f"(c[1]), "+f"(c[2]), "+f"(c[3])
      : "r"(a[0]), "r"(a[1]), "r"(a[2]), "r"(a[3]), "r"(b0), "r"(b1));
}
__device__ __forceinline__ void ldsm_x4(uint32_t& r0, uint32_t& r1, uint32_t& r2, uint32_t& r3,
                                        uint32_t addr) {
    asm volatile("ldmatrix.sync.aligned.m8n8.x4.shared.b16 {%0,%1,%2,%3}, [%4];\n"
      : "=r"(r0), "=r"(r1), "=r"(r2), "=r"(r3) : "r"(addr));
}
__device__ __forceinline__ void ldsm_x4_t(uint32_t& r0, uint32_t& r1, uint32_t& r2, uint32_t& r3,
                                          uint32_t addr) {
    asm volatile("ldmatrix.sync.aligned.m8n8.x4.trans.shared.b16 {%0,%1,%2,%3}, [%4];\n"
      : "=r"(r0), "=r"(r1), "=r"(r2), "=r"(r3) : "r"(addr));
}

// ---------------- fused prep: 6 weight transposes + LN1, one launch --------
// blocks [0, 6912): weight 32x32 transpose-convert tiles
// blocks [6912, 6912+MROWS): LN1 rows
__global__ void __launch_bounds__(256)
prep_kernel(const float* __restrict__ wq, const float* __restrict__ wk,
            const float* __restrict__ wv, const float* __restrict__ wo,
            const float* __restrict__ w1, const float* __restrict__ w2,
            __half* __restrict__ twq, __half* __restrict__ twk,
            __half* __restrict__ twv, __half* __restrict__ two,
            __half* __restrict__ tw1, __half* __restrict__ tw2,
            const float* __restrict__ x, const float* __restrict__ gamma,
            const float* __restrict__ beta, __half* __restrict__ lnout)
{
    __shared__ float sb[32*33];
    const int idx = blockIdx.x;
    const int tid = threadIdx.x;

    if (idx < 6912) {
        // ---- weight transpose-convert ----
        const float* W; __half* Wt; int K, N, tk, tn;
        if (idx < 2304) {
            const int which = idx / 576, r = idx % 576;
            W  = (which == 0) ? wq  : (which == 1) ? wk  : (which == 2) ? wv  : wo;
            Wt = (which == 0) ? twq : (which == 1) ? twk : (which == 2) ? twv : two;
            K = DD; N = DD; tk = r % 24; tn = r / 24;
        } else if (idx < 4608) {
            const int r = idx - 2304;
            W = w1; Wt = tw1; K = DD; N = DFF; tk = r % 24; tn = r / 24;
        } else {
            const int r = idx - 4608;
            W = w2; Wt = tw2; K = DFF; N = DD; tk = r % 96; tn = r / 96;
        }
        const int k0 = tk * 32, n0 = tn * 32;
        const int tx = tid & 31, ty = tid >> 5;       // 32 x 8
        #pragma unroll
        for (int i = 0; i < 32; i += 8)
            sb[(ty + i) * 33 + tx] = W[(size_t)(k0 + ty + i) * N + n0 + tx];
        __syncthreads();
        #pragma unroll
        for (int i = 0; i < 32; i += 8)
            Wt[(size_t)(n0 + ty + i) * K + k0 + tx] = __float2half_rn(sb[tx * 33 + ty + i]);
    } else {
        // ---- LayerNorm row ----
        const int row = idx - 6912;
        const float* xr = x + (size_t)row * DD;
        float a = xr[tid], b = xr[tid + 256], c = xr[tid + 512];
        float s  = a + b + c;
        float ss = a*a + b*b + c*c;
        #pragma unroll
        for (int off = 16; off > 0; off >>= 1) {
            s  += __shfl_xor_sync(0xffffffffu, s,  off);
            ss += __shfl_xor_sync(0xffffffffu, ss, off);
        }
        int wid = tid >> 5, lane = tid & 31;
        if (lane == 0) { sb[wid] = s; sb[8 + wid] = ss; }
        __syncthreads();
        float tot = 0.f, tot2 = 0.f;
        #pragma unroll
        for (int i = 0; i < 8; i++) { tot += sb[i]; tot2 += sb[8 + i]; }
        float mean = tot * (1.0f / DD);
        float var  = tot2 * (1.0f / DD) - mean * mean;
        float rstd = rsqrtf(var + 1e-7f);
        __half* orow = lnout + (size_t)row * DD;
        orow[tid      ] = __float2half_rn(gamma[tid      ] * (a - mean) * rstd + beta[tid      ]);
        orow[tid + 256] = __float2half_rn(gamma[tid + 256] * (b - mean) * rstd + beta[tid + 256]);
        orow[tid + 512] = __float2half_rn(gamma[tid + 512] * (c - mean) * rstd + beta[tid + 512]);
    }
}

// ---------------- LayerNorm (standalone, for LN2) ----------------
__global__ void ln_kernel(const float* __restrict__ x,
                          const float* __restrict__ gamma,
                          const float* __restrict__ beta,
                          __half* __restrict__ out)
{
    int row = blockIdx.x;
    const float* xr = x + (size_t)row * DD;
    int tid = threadIdx.x;

    float a = xr[tid], b = xr[tid + 256], c = xr[tid + 512];
    float s  = a + b + c;
    float ss = a*a + b*b + c*c;
    #pragma unroll
    for (int off = 16; off > 0; off >>= 1) {
        s  += __shfl_xor_sync(0xffffffffu, s,  off);
        ss += __shfl_xor_sync(0xffffffffu, ss, off);
    }
    __shared__ float sh0[8], sh1[8];
    int wid = tid >> 5, lane = tid & 31;
    if (lane == 0) { sh0[wid] = s; sh1[wid] = ss; }
    __syncthreads();
    float tot = 0.f, tot2 = 0.f;
    #pragma unroll
    for (int i = 0; i < 8; i++) { tot += sh0[i]; tot2 += sh1[i]; }
    float mean = tot * (1.0f / DD);
    float var  = tot2 * (1.0f / DD) - mean * mean;
    float rstd = rsqrtf(var + 1e-7f);

    __half* orow = out + (size_t)row * DD;
    orow[tid      ] = __float2half_rn(gamma[tid      ] * (a - mean) * rstd + beta[tid      ]);
    orow[tid + 256] = __float2half_rn(gamma[tid + 256] * (b - mean) * rstd + beta[tid + 256]);
    orow[tid + 512] = __float2half_rn(gamma[tid + 512] * (c - mean) * rstd + beta[tid + 512]);
}

// ---------------- fp16 tensor-core GEMM: 4-stage ring, 1 sync/iter --------
// (unchanged from R9)
#define STAGE_BYTES 20480            // As 128x40x2 + Bs 128x40x2
#define GSMEM (4*STAGE_BYTES)        // 81,920 B

template<int EPI>
__device__ __forceinline__ void hgemm_body(
    const __half* __restrict__ A, const __half* __restrict__ Wt,
    const float* __restrict__ bias, const float* __restrict__ resid,
    void* __restrict__ Cv, int K, int N)
{
    extern __shared__ __align__(16) char dsm[];

    const int tid  = threadIdx.x;
    const int wid  = tid >> 5;
    const int lane = tid & 31;
    const int lr   = lane >> 2;
    const int lc   = lane & 3;
    const int wm   = wid >> 1;        // 0..1
    const int wn   = wid & 1;         // 0..1

    const int rowBase = blockIdx.y * 128;
    const int colBase = blockIdx.x * 128;

    float acc[4][8][4];
    #pragma unroll
    for (int i = 0; i < 4; i++)
        #pragma unroll
        for (int j = 0; j < 8; j++)
            #pragma unroll
            for (int q = 0; q < 4; q++) acc[i][j][q] = 0.f;

    auto load_tiles = [&](int st, int k0) {
        __half (*As)[40] = (__half(*)[40])(dsm + st * STAGE_BYTES);
        __half (*Bs)[40] = (__half(*)[40])(dsm + st * STAGE_BYTES + 10240);
        #pragma unroll
        for (int i = 0; i < 4; i++) {
            int c = tid + i * 128;          // 0..511
            int r = c >> 2, ko = (c & 3) * 8;
            cp_async16(&As[r][ko], A  + (size_t)(rowBase + r) * K + k0 + ko);
            cp_async16(&Bs[r][ko], Wt + (size_t)(colBase + r) * K + k0 + ko);
        }
    };

    const int g = lane >> 3;
    const int grow = lane & 7;
    const int aRowOff = ((g & 1) * 8 + grow);
    const int aColOff = (g >> 1) * 8;
    const int bRowOff = ((g >> 1) * 8 + grow);
    const int bColOff = (g & 1) * 8;

    const int niter = K >> 5;
    load_tiles(0, 0);  CP_COMMIT();
    load_tiles(1, 32); CP_COMMIT();

    for (int it = 0; it < niter; it++) {
        const int st  = it & 3;
        const int pre = it + 2;
        if (pre < niter) {
            load_tiles(pre & 3, pre << 5);
            CP_COMMIT();
            CP_WAIT(2);
        } else if (it + 1 < niter) {
            CP_WAIT(1);
        } else {
            CP_WAIT(0);
        }
        __syncthreads();

        __half (*As)[40] = (__half(*)[40])(dsm + st * STAGE_BYTES);
        __half (*Bs)[40] = (__half(*)[40])(dsm + st * STAGE_BYTES + 10240);
        #pragma unroll
        for (int kc = 0; kc < 2; kc++) {
            const int kk = kc * 16;
            uint32_t bf[8][2];
            #pragma unroll
            for (int jp = 0; jp < 4; jp++) {
                const int n = wn * 64 + jp * 16 + bRowOff;
                uint32_t addr = (uint32_t)__cvta_generic_to_shared(&Bs[n][kk + bColOff]);
                ldsm_x4(bf[2*jp][0], bf[2*jp][1], bf[2*jp+1][0], bf[2*jp+1][1], addr);
            }
            #pragma unroll
            for (int i = 0; i < 4; i++) {
                const int m = wm * 64 + i * 16;
                uint32_t a[4];
                uint32_t addr = (uint32_t)__cvta_generic_to_shared(&As[m + aRowOff][kk + aColOff]);
                ldsm_x4(a[0], a[1], a[2], a[3], addr);
                #pragma unroll
                for (int j = 0; j < 8; j++) mma_f16(acc[i][j], a, bf[j][0], bf[j][1]);
            }
        }
    }

    const int row0 = rowBase + wm * 64;
    const int col0 = colBase + wn * 64;
    __half* Ch = (__half*)Cv;
    float*  Cf = (float*)Cv;
    #pragma unroll
    for (int j = 0; j < 8; j++) {
        const int col = col0 + j * 8 + lc * 2;
        const float b0v = bias[col], b1v = bias[col + 1];
        #pragma unroll
        for (int i = 0; i < 4; i++) {
            const int r0 = row0 + i * 16 + lr;
            float v0 = acc[i][j][0] + b0v;
            float v1 = acc[i][j][1] + b1v;
            float v2 = acc[i][j][2] + b0v;
            float v3 = acc[i][j][3] + b1v;
            if (EPI == 1) {
                v0 += resid[(size_t)r0 * N + col];
                v1 += resid[(size_t)r0 * N + col + 1];
                v2 += resid[(size_t)(r0 + 8) * N + col];
                v3 += resid[(size_t)(r0 + 8) * N + col + 1];
                *(float2*)&Cf[(size_t)r0 * N + col]       = make_float2(v0, v1);
                *(float2*)&Cf[(size_t)(r0 + 8) * N + col] = make_float2(v2, v3);
            } else {
                if (EPI == 2) {
                    v0 = gelu_exact(v0); v1 = gelu_exact(v1);
                    v2 = gelu_exact(v2); v3 = gelu_exact(v3);
                }
                *(__half2*)&Ch[(size_t)r0 * N + col]       = __floats2half2_rn(v0, v1);
                *(__half2*)&Ch[(size_t)(r0 + 8) * N + col] = __floats2half2_rn(v2, v3);
            }
        }
    }
}

template<int EPI>
__global__ void __launch_bounds__(128, 2)
hgemm(const __half* __restrict__ A, const __half* __restrict__ Wt,
      const float* __restrict__ bias, const float* __restrict__ resid,
      void* __restrict__ C, int K, int N)
{
    hgemm_body<EPI>(A, Wt, bias, resid, C, K, N);
}

__global__ void __launch_bounds__(128, 2)
hgemm_qkv(const __half* __restrict__ A,
          const __half* __restrict__ wq, const __half* __restrict__ wk, const __half* __restrict__ wv,
          const float* __restrict__ bq, const float* __restrict__ bk, const float* __restrict__ bv,
          __half* __restrict__ qo, __half* __restrict__ ko, __half* __restrict__ vo,
          int K, int N)
{
    const __half* W  = (blockIdx.z == 0) ? wq : (blockIdx.z == 1) ? wk : wv;
    const float*  bi = (blockIdx.z == 0) ? bq : (blockIdx.z == 1) ? bk : bv;
    __half*       C  = (blockIdx.z == 0) ? qo : (blockIdx.z == 1) ? ko : vo;
    hgemm_body<0>(A, W, bi, nullptr, C, K, N);
}

// ---------------- fp16 causal flash attention: 4-stage KV ring ----------------
// grid (B*H, S/128), 256 threads (8 warps); each warp owns 16 query rows.
// One __syncthreads per key tile (prefetch distance 2, 4 stages).
// Row-sum shuffle reductions deferred until after PV mmas.
#define AST 18432                       // bytes per stage: K 64x72 + V 64x72 halfs
#define ATTN_SMEM (4*AST)               // 73,728 B

__global__ void __launch_bounds__(256)
attn_tc_kernel(const __half* __restrict__ q, const __half* __restrict__ k,
               const __half* __restrict__ v, __half* __restrict__ o)
{
    extern __shared__ __align__(16) char dsm[];
    const uint32_t smem_base = (uint32_t)__cvta_generic_to_shared(dsm);

    const int bh   = blockIdx.x;
    const int b    = bh / HH;
    const int h    = bh % HH;
    const int T    = (gridDim.y - 1) - blockIdx.y;   // heavy tiles first
    const int q0   = T * 128;
    const int tid  = threadIdx.x;
    const int wid  = tid >> 5;
    const int lane = tid & 31;
    const int lr   = lane >> 2;
    const int lc   = lane & 3;
    const size_t headOff = (size_t)h * DKK;
    const size_t bBase   = (size_t)b * SS;

    // ---- stage Q into stage-0 region (128 rows, stride 72 halfs) ----
    {
        __half* Qst = (__half*)dsm;
        #pragma unroll
        for (int i = 0; i < 4; i++) {
            int c = tid + i * 256;                   // 0..1023
            int r = c >> 3, ko = (c & 7) * 8;
            *(uint4*)&Qst[r * 72 + ko] = *(const uint4*)(q + (bBase + q0 + r) * DD + headOff + ko);
        }
    }
    __syncthreads();

    const __half2 qscale = __half2half2(__float2half(0.125f));   // 1/sqrt(64), exact
    uint32_t qf[4][4];
    const int qrow = wid * 16;
    {
        const __half* Qst = (const __half*)dsm;
        #pragma unroll
        for (int kc = 0; kc < 4; kc++) {
            const int kk = kc * 16;
            __half2 t0 = *(__half2*)&Qst[(qrow + lr    ) * 72 + kk + lc * 2];
            __half2 t1 = *(__half2*)&Qst[(qrow + 8 + lr) * 72 + kk + lc * 2];
            __half2 t2 = *(__half2*)&Qst[(qrow + lr    ) * 72 + kk + 8 + lc * 2];
            __half2 t3 = *(__half2*)&Qst[(qrow + 8 + lr) * 72 + kk + 8 + lc * 2];
            t0 = __hmul2(t0, qscale); t1 = __hmul2(t1, qscale);
            t2 = __hmul2(t2, qscale); t3 = __hmul2(t3, qscale);
            qf[kc][0] = *(uint32_t*)&t0; qf[kc][1] = *(uint32_t*)&t1;
            qf[kc][2] = *(uint32_t*)&t2; qf[kc][3] = *(uint32_t*)&t3;
        }
    }
    __syncthreads();   // Q reads done before KV overwrites stage 0

    auto loadKV = [&](int st, int j0) {
        char* base = dsm + st * AST;
        #pragma unroll
        for (int i = 0; i < 2; i++) {
            int c = tid + i * 256;                   // 0..511
            int r = c >> 3, ko = (c & 7) * 8;
            cp_async16(base        + (r * 72 + ko) * 2, k + (bBase + j0 + r) * DD + headOff + ko);
            cp_async16(base + 9216 + (r * 72 + ko) * 2, v + (bBase + j0 + r) * DD + headOff + ko);
        }
    };

    // ldmatrix lane base offsets (bytes)
    const int gq = lane >> 3, rr = lane & 7;
    const uint32_t vlane = ((uint32_t)(((gq & 1) * 8 + rr) * 72 + (gq >> 1) * 8)) * 2;  // trans
    const uint32_t klane = ((uint32_t)(((gq >> 1) * 8 + rr) * 72 + (gq & 1) * 8)) * 2;  // non-trans

    float oacc[8][4];
    #pragma unroll
    for (int nv = 0; nv < 8; nv++)
        #pragma unroll
        for (int t = 0; t < 4; t++) oacc[nv][t] = 0.f;
    float m0 = -1e30f, m1 = -1e30f, l0 = 0.f, l1 = 0.f;

    const int qglob0 = q0 + qrow;
    const int nkt = 2 * T + 2;          // >= 2 always

    loadKV(0, 0);  CP_COMMIT();
    loadKV(1, 64); CP_COMMIT();

    for (int kt = 0; kt < nkt; kt++) {
        const int st = kt & 3;
        const int j0 = kt * 64;
        if (kt + 2 < nkt) {
            loadKV((kt + 2) & 3, (kt + 2) * 64);
            CP_COMMIT();
            CP_WAIT(2);
        } else if (kt + 1 < nkt) {
            CP_WAIT(1);
        } else {
            CP_WAIT(0);
        }
        __syncthreads();

        if (j0 <= qglob0 + 15) {           // else fully masked for this warp
            const uint32_t kb = smem_base + st * AST + klane;
            const uint32_t vb = smem_base + st * AST + 9216 + vlane;

            // ---- S = Q K^T ----
            float sacc[8][4];
            #pragma unroll
            for (int nt = 0; nt < 8; nt++)
                sacc[nt][0] = sacc[nt][1] = sacc[nt][2] = sacc[nt][3] = 0.f;
            #pragma unroll
            for (int kc = 0; kc < 4; kc++) {
                #pragma unroll
                for (int np = 0; np < 4; np++) {
                    uint32_t b0, b1, b2, b3;
                    ldsm_x4(b0, b1, b2, b3, kb + np * 2304 + kc * 32);
                    mma_f16(sacc[2*np    ], qf[kc], b0, b1);
                    mma_f16(sacc[2*np + 1], qf[kc], b2, b3);
                }
            }

            // ---- causal mask (diagonal tiles only) ----
            if (j0 + 63 > qglob0) {
                const int qi0 = qglob0 + lr, qi1 = qi0 + 8;
                #pragma unroll
                for (int nt = 0; nt < 8; nt++) {
                    const int kj = j0 + nt * 8 + lc * 2;
                    if (kj     > qi0) sacc[nt][0] = -1e30f;
                    if (kj + 1 > qi0) sacc[nt][1] = -1e30f;
                    if (kj     > qi1) sacc[nt][2] = -1e30f;
                    if (kj + 1 > qi1) sacc[nt][3] = -1e30f;
                }
            }

            // ---- online softmax (max first — needed before exp) ----
            float mx0 = -1e30f, mx1 = -1e30f;
            #pragma unroll
            for (int nt = 0; nt < 8; nt++) {
                mx0 = fmaxf(mx0, fmaxf(sacc[nt][0], sacc[nt][1]));
                mx1 = fmaxf(mx1, fmaxf(sacc[nt][2], sacc[nt][3]));
            }
            mx0 = fmaxf(mx0, __shfl_xor_sync(0xffffffffu, mx0, 1));
            mx0 = fmaxf(mx0, __shfl_xor_sync(0xffffffffu, mx0, 2));
            mx1 = fmaxf(mx1, __shfl_xor_sync(0xffffffffu, mx1, 1));
            mx1 = fmaxf(mx1, __shfl_xor_sync(0xffffffffu, mx1, 2));

            const float mn0 = fmaxf(m0, mx0);
            const float mn1 = fmaxf(m1, mx1);
            const float sc0 = __expf(m0 - mn0);
            const float sc1 = __expf(m1 - mn1);
            m0 = mn0; m1 = mn1;

            float la0 = 0.f, la1 = 0.f;
            #pragma unroll
            for (int nt = 0; nt < 8; nt++) {
                sacc[nt][0] = __expf(sacc[nt][0] - mn0);
                sacc[nt][1] = __expf(sacc[nt][1] - mn0);
                sacc[nt][2] = __expf(sacc[nt][2] - mn1);
                sacc[nt][3] = __expf(sacc[nt][3] - mn1);
                la0 += sacc[nt][0] + sacc[nt][1];
                la1 += sacc[nt][2] + sacc[nt][3];
            }

            // rescale O accumulators (needs only sc)
            #pragma unroll
            for (int nv = 0; nv < 8; nv++) {
                oacc[nv][0] *= sc0; oacc[nv][1] *= sc0;
                oacc[nv][2] *= sc1; oacc[nv][3] *= sc1;
            }

            // pack P fragments (fp16)
            uint32_t pf[4][4];
            #pragma unroll
            for (int pk = 0; pk < 4; pk++) {
                __half2 h0 = __floats2half2_rn(sacc[2*pk    ][0], sacc[2*pk    ][1]);
                __half2 h1 = __floats2half2_rn(sacc[2*pk    ][2], sacc[2*pk    ][3]);
                __half2 h2 = __floats2half2_rn(sacc[2*pk + 1][0], sacc[2*pk + 1][1]);
                __half2 h3 = __floats2half2_rn(sacc[2*pk + 1][2], sacc[2*pk + 1][3]);
                pf[pk][0] = *(uint32_t*)&h0;
                pf[pk][1] = *(uint32_t*)&h1;
                pf[pk][2] = *(uint32_t*)&h2;
                pf[pk][3] = *(uint32_t*)&h3;
            }

            // ---- O += P V (issue mmas BEFORE the l shuffle reduction) ----
            #pragma unroll
            for (int nh = 0; nh < 4; nh++) {
                #pragma unroll
                for (int pk = 0; pk < 4; pk++) {
                    uint32_t b0, b1, b2, b3;
                    ldsm_x4_t(b0, b1, b2, b3, vb + pk * 2304 + nh * 32);
                    mma_f16(oacc[2*nh    ], pf[pk], b0, b1);
                    mma_f16(oacc[2*nh + 1], pf[pk], b2, b3);
                }
            }

            // deferred l reduction (overlaps SHFL latency with HMMA above)
            la0 += __shfl_xor_sync(0xffffffffu, la0, 1);
            la0 += __shfl_xor_sync(0xffffffffu, la0, 2);
            la1 += __shfl_xor_sync(0xffffffffu, la1, 1);
            la1 += __shfl_xor_sync(0xffffffffu, la1, 2);
            l0 = l0 * sc0 + la0;
            l1 = l1 * sc1 + la1;
        }
    }

    const float inv0 = 1.f / l0;
    const float inv1 = 1.f / l1;
    const size_t r0 = bBase + q0 + qrow + lr;
    #pragma unroll
    for (int nv = 0; nv < 8; nv++) {
        const int col = nv * 8 + lc * 2;
        *(__half2*)&o[r0 * DD + headOff + col] =
            __floats2half2_rn(oacc[nv][0] * inv0, oacc[nv][1] * inv0);
        *(__half2*)&o[(r0 + 8) * DD + headOff + col] =
            __floats2half2_rn(oacc[nv][2] * inv1, oacc[nv][3] * inv1);
    }
}

// ---------------- host launcher ----------------
extern "C" void kernel_launch(void* const* d_in, const int* in_sizes, int n_in,
                              void* d_out, int out_size)
{
    const float* x    = (const float*)d_in[0];
    const float* ln1g = (const float*)d_in[1];
    const float* ln1b = (const float*)d_in[2];
    const float* wq   = (const float*)d_in[3];
    const float* bq   = (const float*)d_in[4];
    const float* wk   = (const float*)d_in[5];
    const float* bk   = (const float*)d_in[6];
    const float* wv   = (const float*)d_in[7];
    const float* bv   = (const float*)d_in[8];
    const float* wo   = (const float*)d_in[9];
    const float* bo   = (const float*)d_in[10];
    const float* ln2g = (const float*)d_in[11];
    const float* ln2b = (const float*)d_in[12];
    const float* w1   = (const float*)d_in[13];
    const float* b1   = (const float*)d_in[14];
    const float* w2   = (const float*)d_in[15];
    const float* b2   = (const float*)d_in[16];
    float* out = (float*)d_out;

    __half *ln1, *qb, *kb, *vb, *attn, *ln2, *ffn1;
    __half *twq, *twk, *twv, *two, *tw1, *tw2;
    float *x1;
    cudaGetSymbolAddress((void**)&ln1,  h_ln1);
    cudaGetSymbolAddress((void**)&qb,   h_q);
    cudaGetSymbolAddress((void**)&kb,   h_k);
    cudaGetSymbolAddress((void**)&vb,   h_v);
    cudaGetSymbolAddress((void**)&attn, h_attn);
    cudaGetSymbolAddress((void**)&x1,   g_x1);
    cudaGetSymbolAddress((void**)&ln2,  h_ln2);
    cudaGetSymbolAddress((void**)&ffn1, h_ffn1);
    cudaGetSymbolAddress((void**)&twq,  h_wq);
    cudaGetSymbolAddress((void**)&twk,  h_wk);
    cudaGetSymbolAddress((void**)&twv,  h_wv);
    cudaGetSymbolAddress((void**)&two,  h_wo);
    cudaGetSymbolAddress((void**)&tw1,  h_w1);
    cudaGetSymbolAddress((void**)&tw2,  h_w2);

    cudaFuncSetAttribute(hgemm<0>,  cudaFuncAttributeMaxDynamicSharedMemorySize, GSMEM);
    cudaFuncSetAttribute(hgemm<1>,  cudaFuncAttributeMaxDynamicSharedMemorySize, GSMEM);
    cudaFuncSetAttribute(hgemm<2>,  cudaFuncAttributeMaxDynamicSharedMemorySize, GSMEM);
    cudaFuncSetAttribute(hgemm_qkv, cudaFuncAttributeMaxDynamicSharedMemorySize, GSMEM);
    cudaFuncSetAttribute(attn_tc_kernel, cudaFuncAttributeMaxDynamicSharedMemorySize, ATTN_SMEM);

    // 0) fused: weight converts + LN1 in one launch
    prep_kernel<<<6912 + MROWS, 256>>>(wq, wk, wv, wo, w1, w2,
                                       twq, twk, twv, two, tw1, tw2,
                                       x, ln1g, ln1b, ln1);

    // 1) QKV projections
    hgemm_qkv<<<dim3(DD / 128, MROWS / 128, 3), 128, GSMEM>>>(
        ln1, twq, twk, twv, bq, bk, bv, qb, kb, vb, DD, DD);

    // 2) causal attention (4-stage KV ring)
    attn_tc_kernel<<<dim3(BB * HH, SS / 128), 256, ATTN_SMEM>>>(qb, kb, vb, attn);

    // 3) O projection + residual -> f32 x1
    hgemm<1><<<dim3(DD / 128, MROWS / 128), 128, GSMEM>>>(attn, two, bo, x, x1, DD, DD);

    // 4) LN2 -> half
    ln_kernel<<<MROWS, 256>>>(x1, ln2g, ln2b, ln2);

    // 5) FFN up + GELU -> half
    hgemm<2><<<dim3(DFF / 128, MROWS / 128), 128, GSMEM>>>(ln2, tw1, b1, nullptr, ffn1, DD, DFF);

    // 6) FFN down + residual -> f32 out
    hgemm<1><<<dim3(DD / 128, MROWS / 128), 128, GSMEM>>>(ffn1, tw2, b2, x1, out, DFF, DD);
}